// round 1
// baseline (speedup 1.0000x reference)
#include <cuda_runtime.h>
#include <math.h>

// ---------------- problem-size scratch (static __device__, no allocs) -------
#define NDMAX 100000
#define EMAX  3200000

__device__ int g_deg[NDMAX];
__device__ int g_rowptr[NDMAX + 1];
__device__ int g_cursor[NDMAX];
__device__ int g_blksum[1024];
__device__ int g_perm[EMAX];

#define LOG_AVG 3.4965075614664802f   // log(33.0) = log(AVG_D + 1)

// ---------------- shared-memory layout for the main kernel (floats) --------
#define SM_WAGG   0            // 2 * 3088 (padded k-pitch: 3072 + 16)
#define SM_W1     6176         // 96*64
#define SM_W2     12320        // 64*32
#define SM_BAGG   14368        // 32
#define SM_B1     14400        // 64
#define SM_B2     14464        // 32
#define SM_W3     14496        // 32
#define SM_WLIN   14528        // 96
#define SM_MISC   14624        // 2: b_lin, b3
#define SM_WORK   14628        // 8 warps * 292
#define SM_WARP_STRIDE 292     // tmp: 2*65=130, x: 96, h1: 64, pad 2
#define SM_TOTAL_FLOATS (SM_WORK + 8 * SM_WARP_STRIDE)

// ---------------- CSR build kernels -----------------------------------------
__global__ void k_zero(int nd) {
    int i = blockIdx.x * blockDim.x + threadIdx.x;
    if (i < nd) g_deg[i] = 0;
}

__global__ void k_hist(const int* __restrict__ dst, int E) {
    int e = blockIdx.x * blockDim.x + threadIdx.x;
    if (e < E) atomicAdd(&g_deg[dst[e]], 1);
}

__global__ void k_scan1(int nd) {
    int tid = threadIdx.x;
    int n = blockIdx.x * 512 + tid;
    int v = (n < nd) ? g_deg[n] : 0;
    int lane = tid & 31, wid = tid >> 5;
    int x = v;
#pragma unroll
    for (int o = 1; o < 32; o <<= 1) {
        int y = __shfl_up_sync(0xffffffffu, x, o);
        if (lane >= o) x += y;
    }
    __shared__ int ws[16];
    if (lane == 31) ws[wid] = x;
    __syncthreads();
    if (wid == 0) {
        int s = (lane < 16) ? ws[lane] : 0;
#pragma unroll
        for (int o = 1; o < 16; o <<= 1) {
            int y = __shfl_up_sync(0xffffffffu, s, o);
            if (lane >= o) s += y;
        }
        if (lane < 16) ws[lane] = s;
    }
    __syncthreads();
    int off = wid ? ws[wid - 1] : 0;
    int incl = x + off;
    if (n < nd) g_rowptr[n] = incl - v;   // exclusive within block
    if (tid == 511) g_blksum[blockIdx.x] = incl;
}

__global__ void k_scan2(int nb) {
    if (threadIdx.x == 0) {
        int acc = 0;
        for (int i = 0; i < nb; i++) { int t = g_blksum[i]; g_blksum[i] = acc; acc += t; }
    }
}

__global__ void k_fix(int nd, int E) {
    int n = blockIdx.x * blockDim.x + threadIdx.x;
    if (n < nd) {
        int r = g_rowptr[n] + g_blksum[n >> 9];
        g_rowptr[n] = r;
        g_cursor[n] = r;
        if (n == 0) g_rowptr[nd] = E;
    }
}

__global__ void k_scatter(const int* __restrict__ src, const int* __restrict__ dst, int E) {
    int e = blockIdx.x * blockDim.x + threadIdx.x;
    if (e < E) {
        int d = dst[e];
        int p = atomicAdd(&g_cursor[d], 1);
        g_perm[p] = src[e];
    }
}

// ---------------- main fused kernel: one warp per dst node ------------------
__global__ __launch_bounds__(256) void k_main(
    const int* __restrict__ Cat_src, const int* __restrict__ Cat_dst,
    const int* __restrict__ label, const float* __restrict__ w,
    const float* __restrict__ W_agg, const float* __restrict__ b_agg,
    const float* __restrict__ w_lin, const float* __restrict__ b_lin,
    const float* __restrict__ W1, const float* __restrict__ b1,
    const float* __restrict__ W2, const float* __restrict__ b2,
    const float* __restrict__ W3, const float* __restrict__ b3,
    float* __restrict__ out, int Nd, int write_label)
{
    extern __shared__ float sm[];
    int tid = threadIdx.x;

    // stage weights into shared (pad W_agg k=1 section by +16 floats for banks)
    for (int i = tid; i < 6144; i += 256) {
        sm[SM_WAGG + i + ((i >= 3072) ? 16 : 0)] = W_agg[i];
        sm[SM_W1 + i] = W1[i];
    }
    for (int i = tid; i < 2048; i += 256) sm[SM_W2 + i] = W2[i];
    if (tid < 32) sm[SM_BAGG + tid] = b_agg[tid];
    if (tid < 64) sm[SM_B1 + tid] = b1[tid];
    if (tid < 32) { sm[SM_B2 + tid] = b2[tid]; sm[SM_W3 + tid] = W3[tid]; }
    if (tid < 96) sm[SM_WLIN + tid] = w_lin[tid];
    if (tid == 0) { sm[SM_MISC + 0] = b_lin[0]; sm[SM_MISC + 1] = b3[0]; }
    __syncthreads();

    int warp = tid >> 5, lane = tid & 31;
    int k = lane >> 4, d = lane & 15;
    float* s_tmp = sm + SM_WORK + warp * SM_WARP_STRIDE;   // 2*65
    float* s_x   = s_tmp + 130;                            // 96
    float* s_h1  = s_x + 96;                               // 64

    int gw = blockIdx.x * 8 + warp;
    int stride = gridDim.x * 8;

    for (int n = gw; n < Nd; n += stride) {
        int base = g_rowptr[n], end = g_rowptr[n + 1];

        // ---- edge reduction (register accumulators per (k,d) lane) ----
        float sum = 0.f, sumsq = 0.f;
        float mn = 3.4e38f, mx = -3.4e38f;
        for (int i = base; i < end; i++) {
            int s = g_perm[i];                                // broadcast
            int4 c = ((const int4*)Cat_src)[s];               // broadcast 16B
            float v0 = w[c.x * 16 + d];
            float v1 = w[c.y * 16 + d];
            float v2 = w[c.z * 16 + d];
            float v3 = w[c.w * 16 + d];
            float me = (v0 + v1 + v2 + v3) * 0.25f;
            float ma = fmaxf(fmaxf(v0, v1), fmaxf(v2, v3));
            float m = k ? ma : me;
            sum += m;
            sumsq = fmaf(m, m, sumsq);
            mn = fminf(mn, m);
            mx = fmaxf(mx, m);
        }

        float deg = (float)(end - base);
        float inv = 1.f / fmaxf(deg, 1.f);
        float mean = sum * inv, mean2 = sumsq * inv;
        bool has = deg > 0.f;
        float vmn = has ? mn : 0.f;
        float vmx = has ? mx : 0.f;
        float sd = sqrtf(fmaxf(mean2 - mean * mean, 0.f) + 1e-5f);
        float logd = logf(deg + 1.f);
        float amp = logd * (1.f / LOG_AVG);
        float att = (logd > 0.f) ? (LOG_AVG / fmaxf(logd, 1e-5f)) : 0.f;

        // tmp = [mean, mn, mx, std] per k, k-pitch 65 (bank-offset)
        s_tmp[k * 65 +  0 + d] = mean;
        s_tmp[k * 65 + 16 + d] = vmn;
        s_tmp[k * 65 + 32 + d] = vmx;
        s_tmp[k * 65 + 48 + d] = sd;
        __syncwarp();

        // ---- PNA einsum: mes[k][d] ----
        const float* Wk = sm + SM_WAGG + k * 3088;
        const float* tk = s_tmp + k * 65;
        float a0 = 0.f, a1 = 0.f, a2 = 0.f;
#pragma unroll
        for (int f = 0; f < 64; f++) {
            float t = tk[f];
            a0 = fmaf(t, Wk[f * 16 + d], a0);
            a1 = fmaf(t, Wk[1024 + f * 16 + d], a1);
            a2 = fmaf(t, Wk[2048 + f * 16 + d], a2);
        }
        float mes = sm[SM_BAGG + k * 16 + d] + a0 + amp * a1 + att * a2;

        // ---- build x = [w[Cat_dst] (4x16), mes (2x16)] ----
        s_x[64 + k * 16 + d] = mes;
        int4 cd = ((const int4*)Cat_dst)[n];
        {
            int j = lane; int fld = j >> 4, dd = j & 15;
            int ci = (fld == 0) ? cd.x : cd.y;
            s_x[j] = w[ci * 16 + dd];
            j = lane + 32; fld = j >> 4; dd = j & 15;
            ci = (fld == 2) ? cd.z : cd.w;
            s_x[j] = w[ci * 16 + dd];
        }
        __syncwarp();

        // ---- DeepFM: lin + fm + deep ----
        float lin = s_x[lane]      * sm[SM_WLIN + lane]
                  + s_x[lane + 32] * sm[SM_WLIN + lane + 32]
                  + s_x[lane + 64] * sm[SM_WLIN + lane + 64];

        float ssum = 0.f, q = 0.f;
#pragma unroll
        for (int f = 0; f < 6; f++) {
            float xv = s_x[f * 16 + d];
            ssum += xv;
            q = fmaf(xv, xv, q);
        }
        float fm = ssum * ssum - q;   // each d counted twice -> scale 0.25 later

        float h1a = sm[SM_B1 + lane], h1b = sm[SM_B1 + lane + 32];
#pragma unroll
        for (int f = 0; f < 96; f++) {
            float xv = s_x[f];
            h1a = fmaf(xv, sm[SM_W1 + f * 64 + lane],      h1a);
            h1b = fmaf(xv, sm[SM_W1 + f * 64 + lane + 32], h1b);
        }
        s_h1[lane]      = fmaxf(h1a, 0.f);
        s_h1[lane + 32] = fmaxf(h1b, 0.f);
        __syncwarp();

        float h2 = sm[SM_B2 + lane];
#pragma unroll
        for (int f = 0; f < 64; f++)
            h2 = fmaf(s_h1[f], sm[SM_W2 + f * 32 + lane], h2);
        h2 = fmaxf(h2, 0.f);
        float dp = h2 * sm[SM_W3 + lane];

        float r1 = lin, r2 = fm, r3 = dp;
#pragma unroll
        for (int o = 16; o; o >>= 1) {
            r1 += __shfl_xor_sync(0xffffffffu, r1, o);
            r2 += __shfl_xor_sync(0xffffffffu, r2, o);
            r3 += __shfl_xor_sync(0xffffffffu, r3, o);
        }
        if (lane == 0) {
            float z = r1 + sm[SM_MISC + 0] + 0.25f * r2 + r3 + sm[SM_MISC + 1];
            out[n] = 1.f / (1.f + expf(-z));
            if (write_label) out[Nd + n] = (float)label[n];
        }
        __syncwarp();
    }
}

// ---------------- launch ----------------------------------------------------
extern "C" void kernel_launch(void* const* d_in, const int* in_sizes, int n_in,
                              void* d_out, int out_size) {
    const int*   Cat_src = (const int*)  d_in[0];
    const int*   Cat_dst = (const int*)  d_in[1];
    const int*   src_ids = (const int*)  d_in[2];
    const int*   dst_ids = (const int*)  d_in[3];
    const int*   label   = (const int*)  d_in[4];
    const float* w       = (const float*)d_in[5];
    const float* W_agg   = (const float*)d_in[6];
    const float* b_agg   = (const float*)d_in[7];
    const float* w_lin   = (const float*)d_in[8];
    const float* b_lin   = (const float*)d_in[9];
    const float* W1      = (const float*)d_in[10];
    const float* b1      = (const float*)d_in[11];
    const float* W2      = (const float*)d_in[12];
    const float* b2      = (const float*)d_in[13];
    const float* W3      = (const float*)d_in[14];
    const float* b3      = (const float*)d_in[15];

    int Nd = in_sizes[1] / 4;    // Cat_dst is [Nd, 4]
    int E  = in_sizes[2];        // src_ids
    float* out = (float*)d_out;
    int write_label = (out_size >= 2 * Nd) ? 1 : 0;

    // CSR build
    k_zero<<<(Nd + 255) / 256, 256>>>(Nd);
    k_hist<<<(E + 255) / 256, 256>>>(dst_ids, E);
    int nb = (Nd + 511) / 512;
    k_scan1<<<nb, 512>>>(Nd);
    k_scan2<<<1, 32>>>(nb);
    k_fix<<<(Nd + 255) / 256, 256>>>(Nd, E);
    k_scatter<<<(E + 255) / 256, 256>>>(src_ids, dst_ids, E);

    // fused gather + PNA + DeepFM
    size_t smem = SM_TOTAL_FLOATS * sizeof(float);
    cudaFuncSetAttribute(k_main, cudaFuncAttributeMaxDynamicSharedMemorySize, (int)smem);
    k_main<<<888, 256, smem>>>(Cat_src, Cat_dst, label, w,
                               W_agg, b_agg, w_lin, b_lin,
                               W1, b1, W2, b2, W3, b3,
                               out, Nd, write_label);
}

// round 2
// speedup vs baseline: 1.0021x; 1.0021x over previous
#include <cuda_runtime.h>
#include <math.h>

// ---------------- problem-size scratch (static __device__, no allocs) -------
#define NDMAX 100000
#define EMAX  3200000

__device__ int g_deg[NDMAX];
__device__ int g_rowptr[NDMAX + 1];
__device__ int g_cursor[NDMAX];
__device__ int g_blksum[1024];
__device__ int g_perm[EMAX];

#define LOG_AVG 3.4965075614664802f   // log(33.0) = log(AVG_D + 1)

// ---------------- shared-memory layout for the main kernel (floats) --------
#define SM_WAGG   0            // 2 * 3088 (padded k-pitch: 3072 + 16)
#define SM_W1     6176         // 96*64
#define SM_W2     12320        // 64*32
#define SM_BAGG   14368        // 32
#define SM_B1     14400        // 64
#define SM_B2     14464        // 32
#define SM_W3     14496        // 32
#define SM_WLIN   14528        // 96
#define SM_MISC   14624        // 2: b_lin, b3
#define SM_WORK   14628        // 8 warps * 292
#define SM_WARP_STRIDE 292     // tmp: 2*65=130, x: 96, h1: 64, pad 2
#define SM_TOTAL_FLOATS (SM_WORK + 8 * SM_WARP_STRIDE)

// ---------------- CSR build kernels -----------------------------------------
__global__ void k_zero(int nd) {
    int i = blockIdx.x * blockDim.x + threadIdx.x;
    if (i < nd) g_deg[i] = 0;
}

__global__ void k_hist(const int* __restrict__ dst, int E) {
    int e = blockIdx.x * blockDim.x + threadIdx.x;
    if (e < E) atomicAdd(&g_deg[dst[e]], 1);
}

__global__ void k_scan1(int nd) {
    int tid = threadIdx.x;
    int n = blockIdx.x * 512 + tid;
    int v = (n < nd) ? g_deg[n] : 0;
    int lane = tid & 31, wid = tid >> 5;
    int x = v;
#pragma unroll
    for (int o = 1; o < 32; o <<= 1) {
        int y = __shfl_up_sync(0xffffffffu, x, o);
        if (lane >= o) x += y;
    }
    __shared__ int ws[16];
    if (lane == 31) ws[wid] = x;
    __syncthreads();
    if (wid == 0) {
        int s = (lane < 16) ? ws[lane] : 0;
#pragma unroll
        for (int o = 1; o < 16; o <<= 1) {
            int y = __shfl_up_sync(0xffffffffu, s, o);
            if (lane >= o) s += y;
        }
        if (lane < 16) ws[lane] = s;
    }
    __syncthreads();
    int off = wid ? ws[wid - 1] : 0;
    int incl = x + off;
    if (n < nd) g_rowptr[n] = incl - v;   // exclusive within block
    if (tid == 511) g_blksum[blockIdx.x] = incl;
}

__global__ void k_scan2(int nb) {
    if (threadIdx.x == 0) {
        int acc = 0;
        for (int i = 0; i < nb; i++) { int t = g_blksum[i]; g_blksum[i] = acc; acc += t; }
    }
}

__global__ void k_fix(int nd, int E) {
    int n = blockIdx.x * blockDim.x + threadIdx.x;
    if (n < nd) {
        int r = g_rowptr[n] + g_blksum[n >> 9];
        g_rowptr[n] = r;
        g_cursor[n] = r;
        if (n == 0) g_rowptr[nd] = E;
    }
}

__global__ void k_scatter(const int* __restrict__ src, const int* __restrict__ dst, int E) {
    int e = blockIdx.x * blockDim.x + threadIdx.x;
    if (e < E) {
        int d = dst[e];
        int p = atomicAdd(&g_cursor[d], 1);
        g_perm[p] = src[e];
    }
}

// ---------------- main fused kernel: one warp per dst node ------------------
__global__ __launch_bounds__(256) void k_main(
    const int* __restrict__ Cat_src, const int* __restrict__ Cat_dst,
    const int* __restrict__ label, const float* __restrict__ w,
    const float* __restrict__ W_agg, const float* __restrict__ b_agg,
    const float* __restrict__ w_lin, const float* __restrict__ b_lin,
    const float* __restrict__ W1, const float* __restrict__ b1,
    const float* __restrict__ W2, const float* __restrict__ b2,
    const float* __restrict__ W3, const float* __restrict__ b3,
    float* __restrict__ out, int Nd, int write_label)
{
    extern __shared__ float sm[];
    int tid = threadIdx.x;

    // stage weights into shared (pad W_agg k=1 section by +16 floats for banks)
    for (int i = tid; i < 6144; i += 256) {
        sm[SM_WAGG + i + ((i >= 3072) ? 16 : 0)] = W_agg[i];
        sm[SM_W1 + i] = W1[i];
    }
    for (int i = tid; i < 2048; i += 256) sm[SM_W2 + i] = W2[i];
    if (tid < 32) sm[SM_BAGG + tid] = b_agg[tid];
    if (tid < 64) sm[SM_B1 + tid] = b1[tid];
    if (tid < 32) { sm[SM_B2 + tid] = b2[tid]; sm[SM_W3 + tid] = W3[tid]; }
    if (tid < 96) sm[SM_WLIN + tid] = w_lin[tid];
    if (tid == 0) { sm[SM_MISC + 0] = b_lin[0]; sm[SM_MISC + 1] = b3[0]; }
    __syncthreads();

    int warp = tid >> 5, lane = tid & 31;
    int k = lane >> 4, d = lane & 15;
    float* s_tmp = sm + SM_WORK + warp * SM_WARP_STRIDE;   // 2*65
    float* s_x   = s_tmp + 130;                            // 96
    float* s_h1  = s_x + 96;                               // 64

    int gw = blockIdx.x * 8 + warp;
    int stride = gridDim.x * 8;

    for (int n = gw; n < Nd; n += stride) {
        int base = g_rowptr[n], end = g_rowptr[n + 1];

        // ---- edge reduction (register accumulators per (k,d) lane) ----
        float sum = 0.f, sumsq = 0.f;
        float mn = 3.4e38f, mx = -3.4e38f;
        for (int i = base; i < end; i++) {
            int s = g_perm[i];                                // broadcast
            int4 c = ((const int4*)Cat_src)[s];               // broadcast 16B
            float v0 = w[c.x * 16 + d];
            float v1 = w[c.y * 16 + d];
            float v2 = w[c.z * 16 + d];
            float v3 = w[c.w * 16 + d];
            float me = (v0 + v1 + v2 + v3) * 0.25f;
            float ma = fmaxf(fmaxf(v0, v1), fmaxf(v2, v3));
            float m = k ? ma : me;
            sum += m;
            sumsq = fmaf(m, m, sumsq);
            mn = fminf(mn, m);
            mx = fmaxf(mx, m);
        }

        float deg = (float)(end - base);
        float inv = 1.f / fmaxf(deg, 1.f);
        float mean = sum * inv, mean2 = sumsq * inv;
        bool has = deg > 0.f;
        float vmn = has ? mn : 0.f;
        float vmx = has ? mx : 0.f;
        float sd = sqrtf(fmaxf(mean2 - mean * mean, 0.f) + 1e-5f);
        float logd = logf(deg + 1.f);
        float amp = logd * (1.f / LOG_AVG);
        float att = (logd > 0.f) ? (LOG_AVG / fmaxf(logd, 1e-5f)) : 0.f;

        // tmp = [mean, mn, mx, std] per k, k-pitch 65 (bank-offset)
        s_tmp[k * 65 +  0 + d] = mean;
        s_tmp[k * 65 + 16 + d] = vmn;
        s_tmp[k * 65 + 32 + d] = vmx;
        s_tmp[k * 65 + 48 + d] = sd;
        __syncwarp();

        // ---- PNA einsum: mes[k][d] ----
        const float* Wk = sm + SM_WAGG + k * 3088;
        const float* tk = s_tmp + k * 65;
        float a0 = 0.f, a1 = 0.f, a2 = 0.f;
#pragma unroll
        for (int f = 0; f < 64; f++) {
            float t = tk[f];
            a0 = fmaf(t, Wk[f * 16 + d], a0);
            a1 = fmaf(t, Wk[1024 + f * 16 + d], a1);
            a2 = fmaf(t, Wk[2048 + f * 16 + d], a2);
        }
        float mes = sm[SM_BAGG + k * 16 + d] + a0 + amp * a1 + att * a2;

        // ---- build x = [w[Cat_dst] (4x16), mes (2x16)] ----
        s_x[64 + k * 16 + d] = mes;
        int4 cd = ((const int4*)Cat_dst)[n];
        {
            int j = lane; int fld = j >> 4, dd = j & 15;
            int ci = (fld == 0) ? cd.x : cd.y;
            s_x[j] = w[ci * 16 + dd];
            j = lane + 32; fld = j >> 4; dd = j & 15;
            ci = (fld == 2) ? cd.z : cd.w;
            s_x[j] = w[ci * 16 + dd];
        }
        __syncwarp();

        // ---- DeepFM: lin + fm + deep ----
        float lin = s_x[lane]      * sm[SM_WLIN + lane]
                  + s_x[lane + 32] * sm[SM_WLIN + lane + 32]
                  + s_x[lane + 64] * sm[SM_WLIN + lane + 64];

        float ssum = 0.f, q = 0.f;
#pragma unroll
        for (int f = 0; f < 6; f++) {
            float xv = s_x[f * 16 + d];
            ssum += xv;
            q = fmaf(xv, xv, q);
        }
        float fm = ssum * ssum - q;   // each d counted twice -> scale 0.25 later

        float h1a = sm[SM_B1 + lane], h1b = sm[SM_B1 + lane + 32];
#pragma unroll
        for (int f = 0; f < 96; f++) {
            float xv = s_x[f];
            h1a = fmaf(xv, sm[SM_W1 + f * 64 + lane],      h1a);
            h1b = fmaf(xv, sm[SM_W1 + f * 64 + lane + 32], h1b);
        }
        s_h1[lane]      = fmaxf(h1a, 0.f);
        s_h1[lane + 32] = fmaxf(h1b, 0.f);
        __syncwarp();

        float h2 = sm[SM_B2 + lane];
#pragma unroll
        for (int f = 0; f < 64; f++)
            h2 = fmaf(s_h1[f], sm[SM_W2 + f * 32 + lane], h2);
        h2 = fmaxf(h2, 0.f);
        float dp = h2 * sm[SM_W3 + lane];

        float r1 = lin, r2 = fm, r3 = dp;
#pragma unroll
        for (int o = 16; o; o >>= 1) {
            r1 += __shfl_xor_sync(0xffffffffu, r1, o);
            r2 += __shfl_xor_sync(0xffffffffu, r2, o);
            r3 += __shfl_xor_sync(0xffffffffu, r3, o);
        }
        if (lane == 0) {
            float z = r1 + sm[SM_MISC + 0] + 0.25f * r2 + r3 + sm[SM_MISC + 1];
            out[n] = 1.f / (1.f + expf(-z));
            if (write_label) out[Nd + n] = (float)label[n];
        }
        __syncwarp();
    }
}

// ---------------- launch ----------------------------------------------------
extern "C" void kernel_launch(void* const* d_in, const int* in_sizes, int n_in,
                              void* d_out, int out_size) {
    const int*   Cat_src = (const int*)  d_in[0];
    const int*   Cat_dst = (const int*)  d_in[1];
    const int*   src_ids = (const int*)  d_in[2];
    const int*   dst_ids = (const int*)  d_in[3];
    const int*   label   = (const int*)  d_in[4];
    const float* w       = (const float*)d_in[5];
    const float* W_agg   = (const float*)d_in[6];
    const float* b_agg   = (const float*)d_in[7];
    const float* w_lin   = (const float*)d_in[8];
    const float* b_lin   = (const float*)d_in[9];
    const float* W1      = (const float*)d_in[10];
    const float* b1      = (const float*)d_in[11];
    const float* W2      = (const float*)d_in[12];
    const float* b2      = (const float*)d_in[13];
    const float* W3      = (const float*)d_in[14];
    const float* b3      = (const float*)d_in[15];

    int Nd = in_sizes[1] / 4;    // Cat_dst is [Nd, 4]
    int E  = in_sizes[2];        // src_ids
    float* out = (float*)d_out;
    int write_label = (out_size >= 2 * Nd) ? 1 : 0;

    // CSR build
    k_zero<<<(Nd + 255) / 256, 256>>>(Nd);
    k_hist<<<(E + 255) / 256, 256>>>(dst_ids, E);
    int nb = (Nd + 511) / 512;
    k_scan1<<<nb, 512>>>(Nd);
    k_scan2<<<1, 32>>>(nb);
    k_fix<<<(Nd + 255) / 256, 256>>>(Nd, E);
    k_scatter<<<(E + 255) / 256, 256>>>(src_ids, dst_ids, E);

    // fused gather + PNA + DeepFM
    size_t smem = SM_TOTAL_FLOATS * sizeof(float);
    cudaFuncSetAttribute(k_main, cudaFuncAttributeMaxDynamicSharedMemorySize, (int)smem);
    k_main<<<888, 256, smem>>>(Cat_src, Cat_dst, label, w,
                               W_agg, b_agg, w_lin, b_lin,
                               W1, b1, W2, b2, W3, b3,
                               out, Nd, write_label);
}

// round 3
// speedup vs baseline: 1.4761x; 1.4730x over previous
#include <cuda_runtime.h>
#include <math.h>

// ---------------- static scratch (no allocs) --------------------------------
#define NSMAX 1000000
#define NDMAX 100000
#define EMAX  3200000

__device__ int   g_deg[NDMAX];
__device__ int   g_rowptr[NDMAX + 1];
__device__ int   g_cursor[NDMAX];
__device__ int   g_blksum[1024];
__device__ int   g_perm[EMAX];
__device__ float g_hsrc[NSMAX * 32];     // [Ns][k*16+d]
__device__ float g_tmp[NDMAX * 128];     // [Nd][k*64 + stat*16 + d]

#define LOG_AVG 3.4965075614664802f      // log(33.0)

// ---------------- k_pre: histogram + h_src precompute ----------------------
__global__ __launch_bounds__(256) void k_pre(
    const int* __restrict__ Cat_src, const int* __restrict__ dst_ids,
    const float* __restrict__ w, int E, int Ns)
{
    int gtid = blockIdx.x * blockDim.x + threadIdx.x;
    int gstride = gridDim.x * blockDim.x;

    // histogram of dst degrees
    for (int e = gtid; e < E; e += gstride)
        atomicAdd(&g_deg[dst_ids[e]], 1);

    // h_src: warp per node
    int lane = threadIdx.x & 31;
    int d = lane & 15;
    int gw = gtid >> 5;
    int wstride = gstride >> 5;
    for (int n = gw; n < Ns; n += wstride) {
        int4 c = ((const int4*)Cat_src)[n];          // broadcast
        float v0 = w[c.x * 16 + d];
        float v1 = w[c.y * 16 + d];
        float v2 = w[c.z * 16 + d];
        float v3 = w[c.w * 16 + d];
        float me = (v0 + v1 + v2 + v3) * 0.25f;
        float ma = fmaxf(fmaxf(v0, v1), fmaxf(v2, v3));
        g_hsrc[n * 32 + lane] = (lane < 16) ? me : ma;
    }
}

// ---------------- CSR scan --------------------------------------------------
__global__ void k_scan1(int nd) {
    int tid = threadIdx.x;
    int n = blockIdx.x * 512 + tid;
    int v = (n < nd) ? g_deg[n] : 0;
    int lane = tid & 31, wid = tid >> 5;
    int x = v;
#pragma unroll
    for (int o = 1; o < 32; o <<= 1) {
        int y = __shfl_up_sync(0xffffffffu, x, o);
        if (lane >= o) x += y;
    }
    __shared__ int ws[16];
    if (lane == 31) ws[wid] = x;
    __syncthreads();
    if (wid == 0) {
        int s = (lane < 16) ? ws[lane] : 0;
#pragma unroll
        for (int o = 1; o < 16; o <<= 1) {
            int y = __shfl_up_sync(0xffffffffu, s, o);
            if (lane >= o) s += y;
        }
        if (lane < 16) ws[lane] = s;
    }
    __syncthreads();
    int off = wid ? ws[wid - 1] : 0;
    int incl = x + off;
    if (n < nd) g_rowptr[n] = incl - v;
    if (tid == 511) g_blksum[blockIdx.x] = incl;
}

__global__ void k_scan2(int nb) {
    if (threadIdx.x == 0) {
        int acc = 0;
        for (int i = 0; i < nb; i++) { int t = g_blksum[i]; g_blksum[i] = acc; acc += t; }
    }
}

__global__ void k_fix(int nd, int E) {
    int n = blockIdx.x * blockDim.x + threadIdx.x;
    if (n < nd) {
        int r = g_rowptr[n] + g_blksum[n >> 9];
        g_rowptr[n] = r;
        g_cursor[n] = r;
        g_deg[n] = 0;                    // ready for next call's histogram
        if (n == 0) g_rowptr[nd] = E;
    }
}

__global__ void k_scatter(const int* __restrict__ src, const int* __restrict__ dst, int E) {
    int e = blockIdx.x * blockDim.x + threadIdx.x;
    if (e < E) {
        int dd = dst[e];
        int p = atomicAdd(&g_cursor[dd], 1);
        g_perm[p] = src[e];
    }
}

// ---------------- k_agg: warp-per-dst edge reduction ------------------------
__global__ __launch_bounds__(256) void k_agg(int Nd)
{
    int lane = threadIdx.x & 31;
    int n = (blockIdx.x * 256 + threadIdx.x) >> 5;
    if (n >= Nd) return;

    int base = g_rowptr[n], end = g_rowptr[n + 1];
    float sum = 0.f, sumsq = 0.f;
    float mn = 3.4e38f, mx = -3.4e38f;

    int i = base;
    for (; i + 1 < end; i += 2) {
        int s0 = g_perm[i];
        int s1 = g_perm[i + 1];
        float a = g_hsrc[s0 * 32 + lane];
        float b = g_hsrc[s1 * 32 + lane];
        sum += a + b;
        sumsq = fmaf(a, a, sumsq);
        sumsq = fmaf(b, b, sumsq);
        mn = fminf(mn, fminf(a, b));
        mx = fmaxf(mx, fmaxf(a, b));
    }
    if (i < end) {
        int s0 = g_perm[i];
        float a = g_hsrc[s0 * 32 + lane];
        sum += a;
        sumsq = fmaf(a, a, sumsq);
        mn = fminf(mn, a);
        mx = fmaxf(mx, a);
    }

    float deg = (float)(end - base);
    float inv = 1.f / fmaxf(deg, 1.f);
    float mean = sum * inv, mean2 = sumsq * inv;
    bool has = deg > 0.f;
    float vmn = has ? mn : 0.f;
    float vmx = has ? mx : 0.f;
    float sd = sqrtf(fmaxf(mean2 - mean * mean, 0.f) + 1e-5f);

    int k = lane >> 4, d = lane & 15;
    float* t = g_tmp + n * 128 + k * 64 + d;
    t[0]  = mean;
    t[16] = vmn;
    t[32] = vmx;
    t[48] = sd;
}

// ---------------- k_mlp: tiled einsum + DeepFM ------------------------------
// shared layout (floats)
#define SM2_WAGG  0        // 2*3088
#define SM2_W1    6176     // 96*64
#define SM2_W2    12320    // 64*32
#define SM2_BAGG  14368    // 32
#define SM2_B1    14400    // 64
#define SM2_B2    14464    // 32
#define SM2_W3    14496    // 32
#define SM2_WLIN  14528    // 96
#define SM2_MISC  14624    // 2
#define SM2_AMP   14628    // 32
#define SM2_ATT   14660    // 32
#define SM2_CD    14692    // 128 (ints in float slots)
#define SM2_TMP   14820    // 32 * 130  (node pitch 130, k pitch 65) -- aliased by h1 (32*66)
#define SM2_X     18980    // 32 * 97
#define SM2_TOTAL (18980 + 32 * 97)   // 22084 floats = 88336 B

__global__ __launch_bounds__(256, 2) void k_mlp(
    const int* __restrict__ Cat_dst, const int* __restrict__ label,
    const float* __restrict__ w,
    const float* __restrict__ W_agg, const float* __restrict__ b_agg,
    const float* __restrict__ w_lin, const float* __restrict__ b_lin,
    const float* __restrict__ W1, const float* __restrict__ b1,
    const float* __restrict__ W2, const float* __restrict__ b2,
    const float* __restrict__ W3, const float* __restrict__ b3,
    float* __restrict__ out, int Nd, int write_label)
{
    extern __shared__ float sm[];
    int tid = threadIdx.x;
    int lane = tid & 31, warp = tid >> 5;
    int k = lane >> 4;
    int* cd_s = (int*)(sm + SM2_CD);

    // stage weights
    for (int i = tid; i < 6144; i += 256) {
        sm[SM2_WAGG + i + ((i >= 3072) ? 16 : 0)] = W_agg[i];
        sm[SM2_W1 + i] = W1[i];
    }
    for (int i = tid; i < 2048; i += 256) sm[SM2_W2 + i] = W2[i];
    if (tid < 32) { sm[SM2_BAGG + tid] = b_agg[tid]; sm[SM2_B2 + tid] = b2[tid]; sm[SM2_W3 + tid] = W3[tid]; }
    if (tid < 64) sm[SM2_B1 + tid] = b1[tid];
    if (tid < 96) sm[SM2_WLIN + tid] = w_lin[tid];
    if (tid == 0) { sm[SM2_MISC + 0] = b_lin[0]; sm[SM2_MISC + 1] = b3[0]; }
    __syncthreads();

    int ntiles = (Nd + 31) >> 5;
    for (int t = blockIdx.x; t < ntiles; t += gridDim.x) {
        int n0 = t << 5;
        __syncthreads();   // smem reuse guard (prev tile fully consumed)

        // ---- P1: stage tmp, Cat_dst, amp/att ----
#pragma unroll
        for (int i = 0; i < 16; i++) {
            int g = tid + i * 256;
            int node = g >> 7, f = g & 127;
            int n = n0 + node; if (n >= Nd) n = Nd - 1;
            sm[SM2_TMP + node * 130 + (f >> 6) * 65 + (f & 63)] = g_tmp[n * 128 + f];
        }
        if (tid < 128) {
            int n = n0 + (tid >> 2); if (n >= Nd) n = Nd - 1;
            cd_s[tid] = Cat_dst[n * 4 + (tid & 3)];
        }
        if (tid < 32) {
            int n = n0 + tid; if (n >= Nd) n = Nd - 1;
            float deg = (float)(g_rowptr[n + 1] - g_rowptr[n]);
            float logd = logf(deg + 1.f);
            sm[SM2_AMP + tid] = logd * (1.f / LOG_AVG);
            sm[SM2_ATT + tid] = (logd > 0.f) ? (LOG_AVG / fmaxf(logd, 1e-5f)) : 0.f;
        }
        __syncthreads();

        // ---- P3: dst-embedding gathers into x[0..63] ----
#pragma unroll
        for (int i = 0; i < 8; i++) {
            int g = tid + i * 256;
            int node = g >> 6, j = g & 63;
            int ci = cd_s[node * 4 + (j >> 4)];
            sm[SM2_X + node * 97 + j] = w[ci * 16 + (j & 15)];
        }

        // ---- P2: PNA einsum, 4 nodes per warp ----
        {
            const float* Wk = sm + SM2_WAGG + k * 3088 + lane - k * 16;  // + f*16 indexed below, d folded
            int nA = warp * 4, nB = nA + 1, nC = nA + 2, nD = nA + 3;
            const float* tA = sm + SM2_TMP + nA * 130 + k * 65;
            const float* tB = tA + 130;
            const float* tC = tB + 130;
            const float* tD = tC + 130;
            float a0A=0.f,a1A=0.f,a2A=0.f, a0B=0.f,a1B=0.f,a2B=0.f;
            float a0C=0.f,a1C=0.f,a2C=0.f, a0D=0.f,a1D=0.f,a2D=0.f;
#pragma unroll 4
            for (int f = 0; f < 64; f++) {
                float w0 = Wk[f * 16];
                float w1 = Wk[1024 + f * 16];
                float w2 = Wk[2048 + f * 16];
                float vA = tA[f], vB = tB[f], vC = tC[f], vD = tD[f];
                a0A = fmaf(vA, w0, a0A); a1A = fmaf(vA, w1, a1A); a2A = fmaf(vA, w2, a2A);
                a0B = fmaf(vB, w0, a0B); a1B = fmaf(vB, w1, a1B); a2B = fmaf(vB, w2, a2B);
                a0C = fmaf(vC, w0, a0C); a1C = fmaf(vC, w1, a1C); a2C = fmaf(vC, w2, a2C);
                a0D = fmaf(vD, w0, a0D); a1D = fmaf(vD, w1, a1D); a2D = fmaf(vD, w2, a2D);
            }
            float bg = sm[SM2_BAGG + lane];
            sm[SM2_X + nA * 97 + 64 + lane] = bg + a0A + sm[SM2_AMP + nA] * a1A + sm[SM2_ATT + nA] * a2A;
            sm[SM2_X + nB * 97 + 64 + lane] = bg + a0B + sm[SM2_AMP + nB] * a1B + sm[SM2_ATT + nB] * a2B;
            sm[SM2_X + nC * 97 + 64 + lane] = bg + a0C + sm[SM2_AMP + nC] * a1C + sm[SM2_ATT + nC] * a2C;
            sm[SM2_X + nD * 97 + 64 + lane] = bg + a0D + sm[SM2_AMP + nD] * a1D + sm[SM2_ATT + nD] * a2D;
        }
        __syncthreads();   // x complete; also tmp dead -> h1 alias safe

        // ---- P4: h1 = relu(x @ W1 + b1), 4 nodes x 64 outs per warp ----
        float* h1_s = sm + SM2_TMP;   // alias, pitch 66
        {
            int nA = warp * 4;
            const float* xA = sm + SM2_X + nA * 97;
            const float* xB = xA + 97;
            const float* xC = xB + 97;
            const float* xD = xC + 97;
            float b1a = sm[SM2_B1 + lane], b1b = sm[SM2_B1 + 32 + lane];
            float hA0=b1a,hA1=b1b, hB0=b1a,hB1=b1b, hC0=b1a,hC1=b1b, hD0=b1a,hD1=b1b;
#pragma unroll 4
            for (int f = 0; f < 96; f++) {
                float wa = sm[SM2_W1 + f * 64 + lane];
                float wb = sm[SM2_W1 + f * 64 + 32 + lane];
                float vA = xA[f], vB = xB[f], vC = xC[f], vD = xD[f];
                hA0 = fmaf(vA, wa, hA0); hA1 = fmaf(vA, wb, hA1);
                hB0 = fmaf(vB, wa, hB0); hB1 = fmaf(vB, wb, hB1);
                hC0 = fmaf(vC, wa, hC0); hC1 = fmaf(vC, wb, hC1);
                hD0 = fmaf(vD, wa, hD0); hD1 = fmaf(vD, wb, hD1);
            }
            h1_s[nA * 66 + lane] = fmaxf(hA0, 0.f);  h1_s[nA * 66 + 32 + lane] = fmaxf(hA1, 0.f);
            h1_s[(nA+1) * 66 + lane] = fmaxf(hB0, 0.f); h1_s[(nA+1) * 66 + 32 + lane] = fmaxf(hB1, 0.f);
            h1_s[(nA+2) * 66 + lane] = fmaxf(hC0, 0.f); h1_s[(nA+2) * 66 + 32 + lane] = fmaxf(hC1, 0.f);
            h1_s[(nA+3) * 66 + lane] = fmaxf(hD0, 0.f); h1_s[(nA+3) * 66 + 32 + lane] = fmaxf(hD1, 0.f);
        }
        __syncwarp();

        // ---- P6: h2 = relu(h1 @ W2 + b2); deep partial = h2 * W3[lane] ----
        float gA, gB, gC, gD;
        {
            int nA = warp * 4;
            const float* hA = h1_s + nA * 66;
            const float* hB = hA + 66;
            const float* hC = hB + 66;
            const float* hD = hC + 66;
            float b2v = sm[SM2_B2 + lane];
            gA = b2v; gB = b2v; gC = b2v; gD = b2v;
#pragma unroll 4
            for (int f = 0; f < 64; f++) {
                float wv = sm[SM2_W2 + f * 32 + lane];
                gA = fmaf(hA[f], wv, gA);
                gB = fmaf(hB[f], wv, gB);
                gC = fmaf(hC[f], wv, gC);
                gD = fmaf(hD[f], wv, gD);
            }
            float w3v = sm[SM2_W3 + lane];
            gA = fmaxf(gA, 0.f) * w3v;
            gB = fmaxf(gB, 0.f) * w3v;
            gC = fmaxf(gC, 0.f) * w3v;
            gD = fmaxf(gD, 0.f) * w3v;
        }

        // ---- P7: lin + fm per node, reduce, output ----
        {
            float wl0 = sm[SM2_WLIN + lane], wl1 = sm[SM2_WLIN + 32 + lane], wl2 = sm[SM2_WLIN + 64 + lane];
            float bl = sm[SM2_MISC + 0] + sm[SM2_MISC + 1];
#pragma unroll
            for (int j = 0; j < 4; j++) {
                int node = warp * 4 + j;
                const float* xs = sm + SM2_X + node * 97;
                float e0 = xs[lane], e1 = xs[32 + lane], e2 = xs[64 + lane];
                float lin_p = e0 * wl0 + e1 * wl1 + e2 * wl2;
                float tsum = e0 + e1 + e2;
                float qsum = e0 * e0 + e1 * e1 + e2 * e2;
                float s = tsum + __shfl_xor_sync(0xffffffffu, tsum, 16);
                float qs = qsum + __shfl_xor_sync(0xffffffffu, qsum, 16);
                float dj = (j == 0) ? gA : (j == 1) ? gB : (j == 2) ? gC : gD;
                float r = lin_p + dj + 0.25f * (s * s - qs);
#pragma unroll
                for (int o = 16; o; o >>= 1)
                    r += __shfl_xor_sync(0xffffffffu, r, o);
                int n = n0 + node;
                if (lane == 0 && n < Nd) {
                    float z = r + bl;
                    out[n] = 1.f / (1.f + expf(-z));
                    if (write_label) out[Nd + n] = (float)label[n];
                }
            }
        }
    }
}

// ---------------- launch ----------------------------------------------------
extern "C" void kernel_launch(void* const* d_in, const int* in_sizes, int n_in,
                              void* d_out, int out_size) {
    const int*   Cat_src = (const int*)  d_in[0];
    const int*   Cat_dst = (const int*)  d_in[1];
    const int*   src_ids = (const int*)  d_in[2];
    const int*   dst_ids = (const int*)  d_in[3];
    const int*   label   = (const int*)  d_in[4];
    const float* w       = (const float*)d_in[5];
    const float* W_agg   = (const float*)d_in[6];
    const float* b_agg   = (const float*)d_in[7];
    const float* w_lin   = (const float*)d_in[8];
    const float* b_lin   = (const float*)d_in[9];
    const float* W1      = (const float*)d_in[10];
    const float* b1      = (const float*)d_in[11];
    const float* W2      = (const float*)d_in[12];
    const float* b2      = (const float*)d_in[13];
    const float* W3      = (const float*)d_in[14];
    const float* b3      = (const float*)d_in[15];

    int Ns = in_sizes[0] / 4;
    int Nd = in_sizes[1] / 4;
    int E  = in_sizes[2];
    float* out = (float*)d_out;
    int write_label = (out_size >= 2 * Nd) ? 1 : 0;

    // 0: histogram + h_src precompute
    k_pre<<<2048, 256>>>(Cat_src, dst_ids, w, E, Ns);
    // 1-3: CSR rowptr scan (+ deg zero for next call inside k_fix)
    int nb = (Nd + 511) / 512;
    k_scan1<<<nb, 512>>>(Nd);
    k_scan2<<<1, 32>>>(nb);
    k_fix<<<(Nd + 255) / 256, 256>>>(Nd, E);
    // 4: edge permutation
    k_scatter<<<(E + 255) / 256, 256>>>(src_ids, dst_ids, E);
    // 5: segment reduction (profiled slot)
    k_agg<<<(Nd + 7) / 8, 256>>>(Nd);
    // 6: einsum + DeepFM
    size_t smem = SM2_TOTAL * sizeof(float);
    cudaFuncSetAttribute(k_mlp, cudaFuncAttributeMaxDynamicSharedMemorySize, (int)smem);
    k_mlp<<<296, 256, smem>>>(Cat_dst, label, w,
                              W_agg, b_agg, w_lin, b_lin,
                              W1, b1, W2, b2, W3, b3,
                              out, Nd, write_label);
}

// round 4
// speedup vs baseline: 1.5028x; 1.0181x over previous
#include <cuda_runtime.h>
#include <cuda_fp16.h>
#include <math.h>

// ---------------- static scratch (no allocs) --------------------------------
#define NSMAX 1000000
#define NDMAX 100000
#define EMAX  3200000

__device__ int    g_deg[NDMAX];
__device__ int    g_rowptr[NDMAX + 1];
__device__ int    g_cursor[NDMAX];
__device__ int    g_blksum[1024];
__device__ int    g_perm[EMAX];
__device__ __half g_hsrc[NSMAX * 32];    // [Ns][k*16+d]  fp16, 64B rows (L2-resident)
__device__ float  g_tmp[NDMAX * 128];    // [Nd][k*64 + stat*16 + d]

#define LOG_AVG 3.4965075614664802f      // log(33.0)

// ---------------- k_pre: histogram + h_src precompute ----------------------
__global__ __launch_bounds__(256) void k_pre(
    const int* __restrict__ Cat_src, const int* __restrict__ dst_ids,
    const float* __restrict__ w, int E, int Ns)
{
    int gtid = blockIdx.x * blockDim.x + threadIdx.x;
    int gstride = gridDim.x * blockDim.x;

    // histogram of dst degrees
    for (int e = gtid; e < E; e += gstride)
        atomicAdd(&g_deg[dst_ids[e]], 1);

    // h_src: warp per node
    int lane = threadIdx.x & 31;
    int d = lane & 15;
    int gw = gtid >> 5;
    int wstride = gstride >> 5;
    for (int n = gw; n < Ns; n += wstride) {
        int4 c = ((const int4*)Cat_src)[n];          // broadcast
        float v0 = w[c.x * 16 + d];
        float v1 = w[c.y * 16 + d];
        float v2 = w[c.z * 16 + d];
        float v3 = w[c.w * 16 + d];
        float me = (v0 + v1 + v2 + v3) * 0.25f;
        float ma = fmaxf(fmaxf(v0, v1), fmaxf(v2, v3));
        g_hsrc[n * 32 + lane] = __float2half_rn((lane < 16) ? me : ma);
    }
}

// ---------------- CSR scan --------------------------------------------------
__global__ void k_scan1(int nd) {
    int tid = threadIdx.x;
    int n = blockIdx.x * 512 + tid;
    int v = (n < nd) ? g_deg[n] : 0;
    int lane = tid & 31, wid = tid >> 5;
    int x = v;
#pragma unroll
    for (int o = 1; o < 32; o <<= 1) {
        int y = __shfl_up_sync(0xffffffffu, x, o);
        if (lane >= o) x += y;
    }
    __shared__ int ws[16];
    if (lane == 31) ws[wid] = x;
    __syncthreads();
    if (wid == 0) {
        int s = (lane < 16) ? ws[lane] : 0;
#pragma unroll
        for (int o = 1; o < 16; o <<= 1) {
            int y = __shfl_up_sync(0xffffffffu, s, o);
            if (lane >= o) s += y;
        }
        if (lane < 16) ws[lane] = s;
    }
    __syncthreads();
    int off = wid ? ws[wid - 1] : 0;
    int incl = x + off;
    if (n < nd) g_rowptr[n] = incl - v;
    if (tid == 511) g_blksum[blockIdx.x] = incl;
}

__global__ void k_scan2(int nb) {
    if (threadIdx.x == 0) {
        int acc = 0;
        for (int i = 0; i < nb; i++) { int t = g_blksum[i]; g_blksum[i] = acc; acc += t; }
    }
}

__global__ void k_fix(int nd, int E) {
    int n = blockIdx.x * blockDim.x + threadIdx.x;
    if (n < nd) {
        int r = g_rowptr[n] + g_blksum[n >> 9];
        g_rowptr[n] = r;
        g_cursor[n] = r;
        g_deg[n] = 0;                    // ready for next call's histogram
        if (n == 0) g_rowptr[nd] = E;
    }
}

__global__ void k_scatter(const int* __restrict__ src, const int* __restrict__ dst, int E) {
    int e = blockIdx.x * blockDim.x + threadIdx.x;
    if (e < E) {
        int dd = dst[e];
        int p = atomicAdd(&g_cursor[dd], 1);
        g_perm[p] = src[e];
    }
}

// ---------------- k_agg: warp-per-dst edge reduction (fp16 h_src) -----------
__global__ __launch_bounds__(256) void k_agg(int Nd)
{
    int lane = threadIdx.x & 31;
    int n = (blockIdx.x * 256 + threadIdx.x) >> 5;
    if (n >= Nd) return;

    int base = g_rowptr[n], end = g_rowptr[n + 1];
    float sum = 0.f, sumsq = 0.f;
    float mn = 3.4e38f, mx = -3.4e38f;

    int i = base;
    for (; i + 3 < end; i += 4) {
        int s0 = g_perm[i];
        int s1 = g_perm[i + 1];
        int s2 = g_perm[i + 2];
        int s3 = g_perm[i + 3];
        float a = __half2float(g_hsrc[s0 * 32 + lane]);
        float b = __half2float(g_hsrc[s1 * 32 + lane]);
        float c = __half2float(g_hsrc[s2 * 32 + lane]);
        float e = __half2float(g_hsrc[s3 * 32 + lane]);
        sum += (a + b) + (c + e);
        sumsq = fmaf(a, a, sumsq);
        sumsq = fmaf(b, b, sumsq);
        sumsq = fmaf(c, c, sumsq);
        sumsq = fmaf(e, e, sumsq);
        mn = fminf(mn, fminf(fminf(a, b), fminf(c, e)));
        mx = fmaxf(mx, fmaxf(fmaxf(a, b), fmaxf(c, e)));
    }
    for (; i < end; i++) {
        int s0 = g_perm[i];
        float a = __half2float(g_hsrc[s0 * 32 + lane]);
        sum += a;
        sumsq = fmaf(a, a, sumsq);
        mn = fminf(mn, a);
        mx = fmaxf(mx, a);
    }

    float deg = (float)(end - base);
    float inv = 1.f / fmaxf(deg, 1.f);
    float mean = sum * inv, mean2 = sumsq * inv;
    bool has = deg > 0.f;
    float vmn = has ? mn : 0.f;
    float vmx = has ? mx : 0.f;
    float sd = sqrtf(fmaxf(mean2 - mean * mean, 0.f) + 1e-5f);

    int k = lane >> 4, d = lane & 15;
    float* t = g_tmp + n * 128 + k * 64 + d;
    t[0]  = mean;
    t[16] = vmn;
    t[32] = vmx;
    t[48] = sd;
}

// ---------------- k_mlp: tiled einsum + DeepFM ------------------------------
// shared layout (floats)
#define SM2_WAGG  0        // 2*3088
#define SM2_W1    6176     // 96*64
#define SM2_W2    12320    // 64*32
#define SM2_BAGG  14368    // 32
#define SM2_B1    14400    // 64
#define SM2_B2    14464    // 32
#define SM2_W3    14496    // 32
#define SM2_WLIN  14528    // 96
#define SM2_MISC  14624    // 2
#define SM2_AMP   14628    // 32
#define SM2_ATT   14660    // 32
#define SM2_CD    14692    // 128 (ints in float slots)
#define SM2_TMP   14820    // 32 * 130  (node pitch 130, k pitch 65) -- aliased by h1 (32*66)
#define SM2_X     18980    // 32 * 97
#define SM2_TOTAL (18980 + 32 * 97)   // 22084 floats = 88336 B

__global__ __launch_bounds__(256, 2) void k_mlp(
    const int* __restrict__ Cat_dst, const int* __restrict__ label,
    const float* __restrict__ w,
    const float* __restrict__ W_agg, const float* __restrict__ b_agg,
    const float* __restrict__ w_lin, const float* __restrict__ b_lin,
    const float* __restrict__ W1, const float* __restrict__ b1,
    const float* __restrict__ W2, const float* __restrict__ b2,
    const float* __restrict__ W3, const float* __restrict__ b3,
    float* __restrict__ out, int Nd, int write_label)
{
    extern __shared__ float sm[];
    int tid = threadIdx.x;
    int lane = tid & 31, warp = tid >> 5;
    int k = lane >> 4;
    int* cd_s = (int*)(sm + SM2_CD);

    // stage weights
    for (int i = tid; i < 6144; i += 256) {
        sm[SM2_WAGG + i + ((i >= 3072) ? 16 : 0)] = W_agg[i];
        sm[SM2_W1 + i] = W1[i];
    }
    for (int i = tid; i < 2048; i += 256) sm[SM2_W2 + i] = W2[i];
    if (tid < 32) { sm[SM2_BAGG + tid] = b_agg[tid]; sm[SM2_B2 + tid] = b2[tid]; sm[SM2_W3 + tid] = W3[tid]; }
    if (tid < 64) sm[SM2_B1 + tid] = b1[tid];
    if (tid < 96) sm[SM2_WLIN + tid] = w_lin[tid];
    if (tid == 0) { sm[SM2_MISC + 0] = b_lin[0]; sm[SM2_MISC + 1] = b3[0]; }
    __syncthreads();

    int ntiles = (Nd + 31) >> 5;
    for (int t = blockIdx.x; t < ntiles; t += gridDim.x) {
        int n0 = t << 5;
        __syncthreads();   // smem reuse guard (prev tile fully consumed)

        // ---- P1: stage tmp, Cat_dst, amp/att ----
#pragma unroll
        for (int i = 0; i < 16; i++) {
            int g = tid + i * 256;
            int node = g >> 7, f = g & 127;
            int n = n0 + node; if (n >= Nd) n = Nd - 1;
            sm[SM2_TMP + node * 130 + (f >> 6) * 65 + (f & 63)] = g_tmp[n * 128 + f];
        }
        if (tid < 128) {
            int n = n0 + (tid >> 2); if (n >= Nd) n = Nd - 1;
            cd_s[tid] = Cat_dst[n * 4 + (tid & 3)];
        }
        if (tid < 32) {
            int n = n0 + tid; if (n >= Nd) n = Nd - 1;
            float deg = (float)(g_rowptr[n + 1] - g_rowptr[n]);
            float logd = logf(deg + 1.f);
            sm[SM2_AMP + tid] = logd * (1.f / LOG_AVG);
            sm[SM2_ATT + tid] = (logd > 0.f) ? (LOG_AVG / fmaxf(logd, 1e-5f)) : 0.f;
        }
        __syncthreads();

        // ---- P3: dst-embedding gathers into x[0..63] ----
#pragma unroll
        for (int i = 0; i < 8; i++) {
            int g = tid + i * 256;
            int node = g >> 6, j = g & 63;
            int ci = cd_s[node * 4 + (j >> 4)];
            sm[SM2_X + node * 97 + j] = w[ci * 16 + (j & 15)];
        }

        // ---- P2: PNA einsum, 4 nodes per warp ----
        {
            const float* Wk = sm + SM2_WAGG + k * 3088 + lane - k * 16;
            int nA = warp * 4, nB = nA + 1, nC = nA + 2, nD = nA + 3;
            const float* tA = sm + SM2_TMP + nA * 130 + k * 65;
            const float* tB = tA + 130;
            const float* tC = tB + 130;
            const float* tD = tC + 130;
            float a0A=0.f,a1A=0.f,a2A=0.f, a0B=0.f,a1B=0.f,a2B=0.f;
            float a0C=0.f,a1C=0.f,a2C=0.f, a0D=0.f,a1D=0.f,a2D=0.f;
#pragma unroll 4
            for (int f = 0; f < 64; f++) {
                float w0 = Wk[f * 16];
                float w1 = Wk[1024 + f * 16];
                float w2 = Wk[2048 + f * 16];
                float vA = tA[f], vB = tB[f], vC = tC[f], vD = tD[f];
                a0A = fmaf(vA, w0, a0A); a1A = fmaf(vA, w1, a1A); a2A = fmaf(vA, w2, a2A);
                a0B = fmaf(vB, w0, a0B); a1B = fmaf(vB, w1, a1B); a2B = fmaf(vB, w2, a2B);
                a0C = fmaf(vC, w0, a0C); a1C = fmaf(vC, w1, a1C); a2C = fmaf(vC, w2, a2C);
                a0D = fmaf(vD, w0, a0D); a1D = fmaf(vD, w1, a1D); a2D = fmaf(vD, w2, a2D);
            }
            float bg = sm[SM2_BAGG + lane];
            sm[SM2_X + nA * 97 + 64 + lane] = bg + a0A + sm[SM2_AMP + nA] * a1A + sm[SM2_ATT + nA] * a2A;
            sm[SM2_X + nB * 97 + 64 + lane] = bg + a0B + sm[SM2_AMP + nB] * a1B + sm[SM2_ATT + nB] * a2B;
            sm[SM2_X + nC * 97 + 64 + lane] = bg + a0C + sm[SM2_AMP + nC] * a1C + sm[SM2_ATT + nC] * a2C;
            sm[SM2_X + nD * 97 + 64 + lane] = bg + a0D + sm[SM2_AMP + nD] * a1D + sm[SM2_ATT + nD] * a2D;
        }
        __syncthreads();   // x complete; also tmp dead -> h1 alias safe

        // ---- P4: h1 = relu(x @ W1 + b1), 4 nodes x 64 outs per warp ----
        float* h1_s = sm + SM2_TMP;   // alias, pitch 66
        {
            int nA = warp * 4;
            const float* xA = sm + SM2_X + nA * 97;
            const float* xB = xA + 97;
            const float* xC = xB + 97;
            const float* xD = xC + 97;
            float b1a = sm[SM2_B1 + lane], b1b = sm[SM2_B1 + 32 + lane];
            float hA0=b1a,hA1=b1b, hB0=b1a,hB1=b1b, hC0=b1a,hC1=b1b, hD0=b1a,hD1=b1b;
#pragma unroll 4
            for (int f = 0; f < 96; f++) {
                float wa = sm[SM2_W1 + f * 64 + lane];
                float wb = sm[SM2_W1 + f * 64 + 32 + lane];
                float vA = xA[f], vB = xB[f], vC = xC[f], vD = xD[f];
                hA0 = fmaf(vA, wa, hA0); hA1 = fmaf(vA, wb, hA1);
                hB0 = fmaf(vB, wa, hB0); hB1 = fmaf(vB, wb, hB1);
                hC0 = fmaf(vC, wa, hC0); hC1 = fmaf(vC, wb, hC1);
                hD0 = fmaf(vD, wa, hD0); hD1 = fmaf(vD, wb, hD1);
            }
            h1_s[nA * 66 + lane] = fmaxf(hA0, 0.f);  h1_s[nA * 66 + 32 + lane] = fmaxf(hA1, 0.f);
            h1_s[(nA+1) * 66 + lane] = fmaxf(hB0, 0.f); h1_s[(nA+1) * 66 + 32 + lane] = fmaxf(hB1, 0.f);
            h1_s[(nA+2) * 66 + lane] = fmaxf(hC0, 0.f); h1_s[(nA+2) * 66 + 32 + lane] = fmaxf(hC1, 0.f);
            h1_s[(nA+3) * 66 + lane] = fmaxf(hD0, 0.f); h1_s[(nA+3) * 66 + 32 + lane] = fmaxf(hD1, 0.f);
        }
        __syncwarp();

        // ---- P6: h2 = relu(h1 @ W2 + b2); deep partial = h2 * W3[lane] ----
        float gA, gB, gC, gD;
        {
            int nA = warp * 4;
            const float* hA = h1_s + nA * 66;
            const float* hB = hA + 66;
            const float* hC = hB + 66;
            const float* hD = hC + 66;
            float b2v = sm[SM2_B2 + lane];
            gA = b2v; gB = b2v; gC = b2v; gD = b2v;
#pragma unroll 4
            for (int f = 0; f < 64; f++) {
                float wv = sm[SM2_W2 + f * 32 + lane];
                gA = fmaf(hA[f], wv, gA);
                gB = fmaf(hB[f], wv, gB);
                gC = fmaf(hC[f], wv, gC);
                gD = fmaf(hD[f], wv, gD);
            }
            float w3v = sm[SM2_W3 + lane];
            gA = fmaxf(gA, 0.f) * w3v;
            gB = fmaxf(gB, 0.f) * w3v;
            gC = fmaxf(gC, 0.f) * w3v;
            gD = fmaxf(gD, 0.f) * w3v;
        }

        // ---- P7: lin + fm per node, reduce, output ----
        {
            float wl0 = sm[SM2_WLIN + lane], wl1 = sm[SM2_WLIN + 32 + lane], wl2 = sm[SM2_WLIN + 64 + lane];
            float bl = sm[SM2_MISC + 0] + sm[SM2_MISC + 1];
#pragma unroll
            for (int j = 0; j < 4; j++) {
                int node = warp * 4 + j;
                const float* xs = sm + SM2_X + node * 97;
                float e0 = xs[lane], e1 = xs[32 + lane], e2 = xs[64 + lane];
                float lin_p = e0 * wl0 + e1 * wl1 + e2 * wl2;
                float tsum = e0 + e1 + e2;
                float qsum = e0 * e0 + e1 * e1 + e2 * e2;
                float s = tsum + __shfl_xor_sync(0xffffffffu, tsum, 16);
                float qs = qsum + __shfl_xor_sync(0xffffffffu, qsum, 16);
                float dj = (j == 0) ? gA : (j == 1) ? gB : (j == 2) ? gC : gD;
                float r = lin_p + dj + 0.25f * (s * s - qs);
#pragma unroll
                for (int o = 16; o; o >>= 1)
                    r += __shfl_xor_sync(0xffffffffu, r, o);
                int n = n0 + node;
                if (lane == 0 && n < Nd) {
                    float z = r + bl;
                    out[n] = 1.f / (1.f + expf(-z));
                    if (write_label) out[Nd + n] = (float)label[n];
                }
            }
        }
    }
}

// ---------------- launch ----------------------------------------------------
extern "C" void kernel_launch(void* const* d_in, const int* in_sizes, int n_in,
                              void* d_out, int out_size) {
    const int*   Cat_src = (const int*)  d_in[0];
    const int*   Cat_dst = (const int*)  d_in[1];
    const int*   src_ids = (const int*)  d_in[2];
    const int*   dst_ids = (const int*)  d_in[3];
    const int*   label   = (const int*)  d_in[4];
    const float* w       = (const float*)d_in[5];
    const float* W_agg   = (const float*)d_in[6];
    const float* b_agg   = (const float*)d_in[7];
    const float* w_lin   = (const float*)d_in[8];
    const float* b_lin   = (const float*)d_in[9];
    const float* W1      = (const float*)d_in[10];
    const float* b1      = (const float*)d_in[11];
    const float* W2      = (const float*)d_in[12];
    const float* b2      = (const float*)d_in[13];
    const float* W3      = (const float*)d_in[14];
    const float* b3      = (const float*)d_in[15];

    int Ns = in_sizes[0] / 4;
    int Nd = in_sizes[1] / 4;
    int E  = in_sizes[2];
    float* out = (float*)d_out;
    int write_label = (out_size >= 2 * Nd) ? 1 : 0;

    // 0: histogram + h_src precompute
    k_pre<<<2048, 256>>>(Cat_src, dst_ids, w, E, Ns);
    // 1-3: CSR rowptr scan (+ deg zero for next call inside k_fix)
    int nb = (Nd + 511) / 512;
    k_scan1<<<nb, 512>>>(Nd);
    k_scan2<<<1, 32>>>(nb);
    k_fix<<<(Nd + 255) / 256, 256>>>(Nd, E);
    // 4: edge permutation
    k_scatter<<<(E + 255) / 256, 256>>>(src_ids, dst_ids, E);
    // 5: segment reduction
    k_agg<<<(Nd + 7) / 8, 256>>>(Nd);
    // 6: einsum + DeepFM
    size_t smem = SM2_TOTAL * sizeof(float);
    cudaFuncSetAttribute(k_mlp, cudaFuncAttributeMaxDynamicSharedMemorySize, (int)smem);
    k_mlp<<<296, 256, smem>>>(Cat_dst, label, w,
                              W_agg, b_agg, w_lin, b_lin,
                              W1, b1, W2, b2, W3, b3,
                              out, Nd, write_label);
}

// round 5
// speedup vs baseline: 1.6346x; 1.0877x over previous
#include <cuda_runtime.h>
#include <cuda_fp16.h>
#include <math.h>

typedef unsigned long long ull;

// ---------------- static scratch (no allocs) --------------------------------
#define NSMAX 1000000
#define NDMAX 100000
#define EMAX  3200000

__device__ int    g_deg[NDMAX];
__device__ int    g_rowptr[NDMAX + 1];
__device__ int    g_cursor[NDMAX];
__device__ int    g_blksum[1024];
__device__ int    g_perm[EMAX];
__device__ __half g_hsrc[NSMAX * 32];    // [Ns][k*16+d]  fp16, 64B rows (L2-resident)
__device__ float  g_tmp[NDMAX * 128];    // [Nd][k*64 + stat*16 + d]

#define LOG_AVG 3.4965075614664802f      // log(33.0)

// ---------------- f32x2 helpers ---------------------------------------------
__device__ __forceinline__ void fma2(ull& acc, ull a, ull b) {
    asm("fma.rn.f32x2 %0, %1, %2, %0;" : "+l"(acc) : "l"(a), "l"(b));
}
__device__ __forceinline__ float hsum2(ull v) {
    float lo, hi;
    asm("mov.b64 {%0,%1}, %2;" : "=f"(lo), "=f"(hi) : "l"(v));
    return lo + hi;
}

// ---------------- k_pre: histogram + h_src precompute ----------------------
__global__ __launch_bounds__(256) void k_pre(
    const int* __restrict__ Cat_src, const int* __restrict__ dst_ids,
    const float* __restrict__ w, int E, int Ns)
{
    int gtid = blockIdx.x * blockDim.x + threadIdx.x;
    int gstride = gridDim.x * blockDim.x;

    for (int e = gtid; e < E; e += gstride)
        atomicAdd(&g_deg[dst_ids[e]], 1);

    int lane = threadIdx.x & 31;
    int d = lane & 15;
    int gw = gtid >> 5;
    int wstride = gstride >> 5;
    for (int n = gw; n < Ns; n += wstride) {
        int4 c = ((const int4*)Cat_src)[n];          // broadcast
        float v0 = w[c.x * 16 + d];
        float v1 = w[c.y * 16 + d];
        float v2 = w[c.z * 16 + d];
        float v3 = w[c.w * 16 + d];
        float me = (v0 + v1 + v2 + v3) * 0.25f;
        float ma = fmaxf(fmaxf(v0, v1), fmaxf(v2, v3));
        g_hsrc[n * 32 + lane] = __float2half_rn((lane < 16) ? me : ma);
    }
}

// ---------------- CSR scan --------------------------------------------------
__global__ void k_scan1(int nd) {
    int tid = threadIdx.x;
    int n = blockIdx.x * 512 + tid;
    int v = (n < nd) ? g_deg[n] : 0;
    int lane = tid & 31, wid = tid >> 5;
    int x = v;
#pragma unroll
    for (int o = 1; o < 32; o <<= 1) {
        int y = __shfl_up_sync(0xffffffffu, x, o);
        if (lane >= o) x += y;
    }
    __shared__ int ws[16];
    if (lane == 31) ws[wid] = x;
    __syncthreads();
    if (wid == 0) {
        int s = (lane < 16) ? ws[lane] : 0;
#pragma unroll
        for (int o = 1; o < 16; o <<= 1) {
            int y = __shfl_up_sync(0xffffffffu, s, o);
            if (lane >= o) s += y;
        }
        if (lane < 16) ws[lane] = s;
    }
    __syncthreads();
    int off = wid ? ws[wid - 1] : 0;
    int incl = x + off;
    if (n < nd) g_rowptr[n] = incl - v;
    if (tid == 511) g_blksum[blockIdx.x] = incl;   // RAW block total
}

// k_fix: adds blksum prefix (computed in-block), inits cursor, zeroes deg
__global__ __launch_bounds__(256) void k_fix(int nd, int E) {
    __shared__ int pre_s;
    int bs = blockIdx.x >> 1;        // scan1 block (512-wide) index
    if (threadIdx.x < 32) {
        int acc = 0;
        for (int i = threadIdx.x; i < bs; i += 32) acc += g_blksum[i];
#pragma unroll
        for (int o = 16; o; o >>= 1) acc += __shfl_xor_sync(0xffffffffu, acc, o);
        if (threadIdx.x == 0) pre_s = acc;
    }
    __syncthreads();
    int pre = pre_s;
    int n = blockIdx.x * 256 + threadIdx.x;
    if (n < nd) {
        int r = g_rowptr[n] + pre;
        g_rowptr[n] = r;
        g_cursor[n] = r;
        g_deg[n] = 0;
        if (n == 0) g_rowptr[nd] = E;
    }
}

__global__ void k_scatter(const int* __restrict__ src, const int* __restrict__ dst, int E) {
    int e = blockIdx.x * blockDim.x + threadIdx.x;
    if (e < E) {
        int dd = dst[e];
        int p = atomicAdd(&g_cursor[dd], 1);
        g_perm[p] = src[e];
    }
}

// ---------------- k_agg: 2 dst-nodes per warp, half2 loads ------------------
__global__ __launch_bounds__(256) void k_agg(int Nd)
{
    int lane = threadIdx.x & 31;
    int half = lane >> 4;            // node within warp
    int j = lane & 15;               // channel pair: channels 2j, 2j+1
    int n = (((blockIdx.x * 256 + threadIdx.x) >> 5) << 1) + half;
    if (n >= Nd) return;

    int base = g_rowptr[n], end = g_rowptr[n + 1];
    const __half2* H = (const __half2*)g_hsrc;

    float s0f = 0.f, s1f = 0.f, q0 = 0.f, q1 = 0.f;
    float mn0 = 3.4e38f, mn1 = 3.4e38f, mx0 = -3.4e38f, mx1 = -3.4e38f;

    int i = base;
    for (; i + 1 < end; i += 2) {
        int e0 = g_perm[i];
        int e1 = g_perm[i + 1];
        float2 a = __half22float2(H[e0 * 16 + j]);
        float2 b = __half22float2(H[e1 * 16 + j]);
        s0f += a.x + b.x;  s1f += a.y + b.y;
        q0 = fmaf(a.x, a.x, q0); q0 = fmaf(b.x, b.x, q0);
        q1 = fmaf(a.y, a.y, q1); q1 = fmaf(b.y, b.y, q1);
        mn0 = fminf(mn0, fminf(a.x, b.x)); mn1 = fminf(mn1, fminf(a.y, b.y));
        mx0 = fmaxf(mx0, fmaxf(a.x, b.x)); mx1 = fmaxf(mx1, fmaxf(a.y, b.y));
    }
    if (i < end) {
        int e0 = g_perm[i];
        float2 a = __half22float2(H[e0 * 16 + j]);
        s0f += a.x; s1f += a.y;
        q0 = fmaf(a.x, a.x, q0); q1 = fmaf(a.y, a.y, q1);
        mn0 = fminf(mn0, a.x); mn1 = fminf(mn1, a.y);
        mx0 = fmaxf(mx0, a.x); mx1 = fmaxf(mx1, a.y);
    }

    float deg = (float)(end - base);
    float inv = 1.f / fmaxf(deg, 1.f);
    bool has = deg > 0.f;
    float mean0 = s0f * inv, mean1 = s1f * inv;
    float sd0 = sqrtf(fmaxf(q0 * inv - mean0 * mean0, 0.f) + 1e-5f);
    float sd1 = sqrtf(fmaxf(q1 * inv - mean1 * mean1, 0.f) + 1e-5f);
    if (!has) { mn0 = mn1 = mx0 = mx1 = 0.f; }

    int k = j >> 3;                   // both channels in same k-block
    int d0 = (2 * j) & 15;
    float* t = g_tmp + n * 128 + k * 64 + d0;
    t[0]  = mean0;  t[1]  = mean1;
    t[16] = mn0;    t[17] = mn1;
    t[32] = mx0;    t[33] = mx1;
    t[48] = sd0;    t[49] = sd1;
}

// ---------------- k_mlp: tiled einsum + DeepFM, f32x2 packed ----------------
// shared layout (floats). Weight matrices stored f-PAIR interleaved:
//   W_agg: [k][sec][f2][d][2]  k-pitch 3088, sec*1024, f2*32, d*2, (f&1)
//   W1:    [f2][o][2]          f2*128 + o*2 + (f&1)
//   W2:    [f2][o][2]          f2*64  + o*2 + (f&1)
#define SM2_WAGG  0        // 2*3088
#define SM2_W1    6176     // 96*64
#define SM2_W2    12320    // 64*32
#define SM2_BAGG  14368    // 32
#define SM2_B1    14400    // 64
#define SM2_B2    14464    // 32
#define SM2_W3    14496    // 32
#define SM2_WLIN  14528    // 96
#define SM2_MISC  14624    // 2
#define SM2_AMP   14628    // 32
#define SM2_ATT   14660    // 32
#define SM2_CD    14692    // 128 ints
#define SM2_TMP   14820    // 32 * 132 (node pitch 132, k pitch 66) -- aliased by h1 (pitch 66)
#define SM2_X     19044    // 32 * 98
#define SM2_TOTAL (19044 + 32 * 98)   // 22180 floats = 88720 B

__global__ __launch_bounds__(256, 2) void k_mlp(
    const int* __restrict__ Cat_dst, const int* __restrict__ label,
    const float* __restrict__ w,
    const float* __restrict__ W_agg, const float* __restrict__ b_agg,
    const float* __restrict__ w_lin, const float* __restrict__ b_lin,
    const float* __restrict__ W1, const float* __restrict__ b1,
    const float* __restrict__ W2, const float* __restrict__ b2,
    const float* __restrict__ W3, const float* __restrict__ b3,
    float* __restrict__ out, int Nd, int write_label)
{
    extern __shared__ float sm[];
    int tid = threadIdx.x;
    int lane = tid & 31, warp = tid >> 5;
    int k = lane >> 4, d = lane & 15;
    int* cd_s = (int*)(sm + SM2_CD);

    // ---- stage weights (pair-interleaved) ----
    for (int i = tid; i < 6144; i += 256) {
        // W_agg: i = k*3072 + sec*1024 + f*16 + d
        int kk = i / 3072;
        int r = i - kk * 3072;
        int sec = r >> 10;
        int rr = r & 1023;
        int ff = rr >> 4, dd = rr & 15;
        sm[SM2_WAGG + kk * 3088 + sec * 1024 + (ff >> 1) * 32 + dd * 2 + (ff & 1)] = W_agg[i];
        // W1: i = f*64 + o
        int f1 = i >> 6, o1 = i & 63;
        sm[SM2_W1 + (f1 >> 1) * 128 + o1 * 2 + (f1 & 1)] = W1[i];
    }
    for (int i = tid; i < 2048; i += 256) {
        int f2_ = i >> 5, o2 = i & 31;
        sm[SM2_W2 + (f2_ >> 1) * 64 + o2 * 2 + (f2_ & 1)] = W2[i];
    }
    if (tid < 32) { sm[SM2_BAGG + tid] = b_agg[tid]; sm[SM2_B2 + tid] = b2[tid]; sm[SM2_W3 + tid] = W3[tid]; }
    if (tid < 64) sm[SM2_B1 + tid] = b1[tid];
    if (tid < 96) sm[SM2_WLIN + tid] = w_lin[tid];
    if (tid == 0) { sm[SM2_MISC + 0] = b_lin[0]; sm[SM2_MISC + 1] = b3[0]; }
    __syncthreads();

    int ntiles = (Nd + 31) >> 5;
    for (int t = blockIdx.x; t < ntiles; t += gridDim.x) {
        int n0 = t << 5;
        __syncthreads();   // smem reuse guard

        // ---- P1: stage tmp, Cat_dst, amp/att ----
#pragma unroll
        for (int i = 0; i < 16; i++) {
            int g = tid + i * 256;
            int node = g >> 7, f = g & 127;
            int n = n0 + node; if (n >= Nd) n = Nd - 1;
            sm[SM2_TMP + node * 132 + (f >> 6) * 66 + (f & 63)] = g_tmp[n * 128 + f];
        }
        if (tid < 128) {
            int n = n0 + (tid >> 2); if (n >= Nd) n = Nd - 1;
            cd_s[tid] = Cat_dst[n * 4 + (tid & 3)];
        }
        if (tid < 32) {
            int n = n0 + tid; if (n >= Nd) n = Nd - 1;
            float deg = (float)(g_rowptr[n + 1] - g_rowptr[n]);
            float logd = logf(deg + 1.f);
            sm[SM2_AMP + tid] = logd * (1.f / LOG_AVG);
            sm[SM2_ATT + tid] = (logd > 0.f) ? (LOG_AVG / fmaxf(logd, 1e-5f)) : 0.f;
        }
        __syncthreads();

        // ---- P3: dst-embedding gathers into x[0..63] ----
#pragma unroll
        for (int i = 0; i < 8; i++) {
            int g = tid + i * 256;
            int node = g >> 6, j = g & 63;
            int ci = cd_s[node * 4 + (j >> 4)];
            sm[SM2_X + node * 98 + j] = w[ci * 16 + (j & 15)];
        }

        // ---- P2: PNA einsum (f32x2), 4 nodes per warp ----
        {
            const ull* W0 = (const ull*)(sm + SM2_WAGG + k * 3088) + d;   // +f2*16; sections +512, +1024
            int nA = warp * 4;
            const ull* tA2 = (const ull*)(sm + SM2_TMP + nA * 132 + k * 66);
            const ull* tB2 = (const ull*)((const float*)tA2 + 132);
            const ull* tC2 = (const ull*)((const float*)tB2 + 132);
            const ull* tD2 = (const ull*)((const float*)tC2 + 132);
            ull a0A=0,a1A=0,a2A=0, a0B=0,a1B=0,a2B=0;
            ull a0C=0,a1C=0,a2C=0, a0D=0,a1D=0,a2D=0;
#pragma unroll 4
            for (int f2 = 0; f2 < 32; f2++) {
                ull w0 = W0[f2 * 16];
                ull w1 = W0[512 + f2 * 16];
                ull w2 = W0[1024 + f2 * 16];
                ull vA = tA2[f2], vB = tB2[f2], vC = tC2[f2], vD = tD2[f2];
                fma2(a0A, vA, w0); fma2(a1A, vA, w1); fma2(a2A, vA, w2);
                fma2(a0B, vB, w0); fma2(a1B, vB, w1); fma2(a2B, vB, w2);
                fma2(a0C, vC, w0); fma2(a1C, vC, w1); fma2(a2C, vC, w2);
                fma2(a0D, vD, w0); fma2(a1D, vD, w1); fma2(a2D, vD, w2);
            }
            float bg = sm[SM2_BAGG + lane];
            sm[SM2_X + nA * 98 + 64 + lane]       = bg + hsum2(a0A) + sm[SM2_AMP + nA] * hsum2(a1A) + sm[SM2_ATT + nA] * hsum2(a2A);
            sm[SM2_X + (nA+1) * 98 + 64 + lane]   = bg + hsum2(a0B) + sm[SM2_AMP + nA+1] * hsum2(a1B) + sm[SM2_ATT + nA+1] * hsum2(a2B);
            sm[SM2_X + (nA+2) * 98 + 64 + lane]   = bg + hsum2(a0C) + sm[SM2_AMP + nA+2] * hsum2(a1C) + sm[SM2_ATT + nA+2] * hsum2(a2C);
            sm[SM2_X + (nA+3) * 98 + 64 + lane]   = bg + hsum2(a0D) + sm[SM2_AMP + nA+3] * hsum2(a1D) + sm[SM2_ATT + nA+3] * hsum2(a2D);
        }
        __syncthreads();   // x complete; tmp dead -> h1 alias safe

        // ---- P4: h1 = relu(x @ W1 + b1), f32x2 ----
        float* h1_s = sm + SM2_TMP;   // alias, pitch 66
        {
            int nA = warp * 4;
            const ull* W1a = (const ull*)(sm + SM2_W1) + lane;        // +f2*64
            const ull* W1b = W1a + 32;
            const ull* xA2 = (const ull*)(sm + SM2_X + nA * 98);
            const ull* xB2 = (const ull*)(sm + SM2_X + (nA+1) * 98);
            const ull* xC2 = (const ull*)(sm + SM2_X + (nA+2) * 98);
            const ull* xD2 = (const ull*)(sm + SM2_X + (nA+3) * 98);
            ull hA0=0,hA1=0, hB0=0,hB1=0, hC0=0,hC1=0, hD0=0,hD1=0;
#pragma unroll 4
            for (int f2 = 0; f2 < 48; f2++) {
                ull wa = W1a[f2 * 64];
                ull wb = W1b[f2 * 64];
                ull vA = xA2[f2], vB = xB2[f2], vC = xC2[f2], vD = xD2[f2];
                fma2(hA0, vA, wa); fma2(hA1, vA, wb);
                fma2(hB0, vB, wa); fma2(hB1, vB, wb);
                fma2(hC0, vC, wa); fma2(hC1, vC, wb);
                fma2(hD0, vD, wa); fma2(hD1, vD, wb);
            }
            float b1a = sm[SM2_B1 + lane], b1b = sm[SM2_B1 + 32 + lane];
            h1_s[warp*4*66       + lane] = fmaxf(hsum2(hA0) + b1a, 0.f);
            h1_s[warp*4*66       + 32 + lane] = fmaxf(hsum2(hA1) + b1b, 0.f);
            h1_s[(warp*4+1)*66   + lane] = fmaxf(hsum2(hB0) + b1a, 0.f);
            h1_s[(warp*4+1)*66   + 32 + lane] = fmaxf(hsum2(hB1) + b1b, 0.f);
            h1_s[(warp*4+2)*66   + lane] = fmaxf(hsum2(hC0) + b1a, 0.f);
            h1_s[(warp*4+2)*66   + 32 + lane] = fmaxf(hsum2(hC1) + b1b, 0.f);
            h1_s[(warp*4+3)*66   + lane] = fmaxf(hsum2(hD0) + b1a, 0.f);
            h1_s[(warp*4+3)*66   + 32 + lane] = fmaxf(hsum2(hD1) + b1b, 0.f);
        }
        __syncwarp();

        // ---- P6: h2 = relu(h1 @ W2 + b2); deep partial ----
        float gA, gB, gC, gD;
        {
            int nA = warp * 4;
            const ull* W2p = (const ull*)(sm + SM2_W2) + lane;        // +f2*32
            const ull* hA2 = (const ull*)(h1_s + nA * 66);
            const ull* hB2 = (const ull*)(h1_s + (nA+1) * 66);
            const ull* hC2 = (const ull*)(h1_s + (nA+2) * 66);
            const ull* hD2 = (const ull*)(h1_s + (nA+3) * 66);
            ull aA=0, aB=0, aC=0, aD=0;
#pragma unroll 4
            for (int f2 = 0; f2 < 32; f2++) {
                ull wv = W2p[f2 * 32];
                fma2(aA, hA2[f2], wv);
                fma2(aB, hB2[f2], wv);
                fma2(aC, hC2[f2], wv);
                fma2(aD, hD2[f2], wv);
            }
            float b2v = sm[SM2_B2 + lane];
            float w3v = sm[SM2_W3 + lane];
            gA = fmaxf(hsum2(aA) + b2v, 0.f) * w3v;
            gB = fmaxf(hsum2(aB) + b2v, 0.f) * w3v;
            gC = fmaxf(hsum2(aC) + b2v, 0.f) * w3v;
            gD = fmaxf(hsum2(aD) + b2v, 0.f) * w3v;
        }

        // ---- P7: lin + fm per node, reduce, output ----
        {
            float wl0 = sm[SM2_WLIN + lane], wl1 = sm[SM2_WLIN + 32 + lane], wl2 = sm[SM2_WLIN + 64 + lane];
            float bl = sm[SM2_MISC + 0] + sm[SM2_MISC + 1];
#pragma unroll
            for (int j = 0; j < 4; j++) {
                int node = warp * 4 + j;
                const float* xs = sm + SM2_X + node * 98;
                float e0 = xs[lane], e1 = xs[32 + lane], e2 = xs[64 + lane];
                float lin_p = e0 * wl0 + e1 * wl1 + e2 * wl2;
                float tsum = e0 + e1 + e2;
                float qsum = e0 * e0 + e1 * e1 + e2 * e2;
                float s = tsum + __shfl_xor_sync(0xffffffffu, tsum, 16);
                float qs = qsum + __shfl_xor_sync(0xffffffffu, qsum, 16);
                float dj = (j == 0) ? gA : (j == 1) ? gB : (j == 2) ? gC : gD;
                float r = lin_p + dj + 0.25f * (s * s - qs);
#pragma unroll
                for (int o = 16; o; o >>= 1)
                    r += __shfl_xor_sync(0xffffffffu, r, o);
                int n = n0 + node;
                if (lane == 0 && n < Nd) {
                    float z = r + bl;
                    out[n] = 1.f / (1.f + expf(-z));
                    if (write_label) out[Nd + n] = (float)label[n];
                }
            }
        }
    }
}

// ---------------- launch ----------------------------------------------------
extern "C" void kernel_launch(void* const* d_in, const int* in_sizes, int n_in,
                              void* d_out, int out_size) {
    const int*   Cat_src = (const int*)  d_in[0];
    const int*   Cat_dst = (const int*)  d_in[1];
    const int*   src_ids = (const int*)  d_in[2];
    const int*   dst_ids = (const int*)  d_in[3];
    const int*   label   = (const int*)  d_in[4];
    const float* w       = (const float*)d_in[5];
    const float* W_agg   = (const float*)d_in[6];
    const float* b_agg   = (const float*)d_in[7];
    const float* w_lin   = (const float*)d_in[8];
    const float* b_lin   = (const float*)d_in[9];
    const float* W1      = (const float*)d_in[10];
    const float* b1      = (const float*)d_in[11];
    const float* W2      = (const float*)d_in[12];
    const float* b2      = (const float*)d_in[13];
    const float* W3      = (const float*)d_in[14];
    const float* b3      = (const float*)d_in[15];

    int Ns = in_sizes[0] / 4;
    int Nd = in_sizes[1] / 4;
    int E  = in_sizes[2];
    float* out = (float*)d_out;
    int write_label = (out_size >= 2 * Nd) ? 1 : 0;

    // 0: histogram + h_src precompute
    k_pre<<<2048, 256>>>(Cat_src, dst_ids, w, E, Ns);
    // 1-2: CSR rowptr scan (blksum prefix folded into k_fix)
    int nb = (Nd + 511) / 512;
    k_scan1<<<nb, 512>>>(Nd);
    k_fix<<<(Nd + 255) / 256, 256>>>(Nd, E);
    // 3: edge permutation
    k_scatter<<<(E + 255) / 256, 256>>>(src_ids, dst_ids, E);
    // 4: segment reduction (2 nodes/warp)
    k_agg<<<(Nd + 15) / 16, 256>>>(Nd);
    // 5: einsum + DeepFM (f32x2)
    size_t smem = SM2_TOTAL * sizeof(float);
    cudaFuncSetAttribute(k_mlp, cudaFuncAttributeMaxDynamicSharedMemorySize, (int)smem);
    k_mlp<<<296, 256, smem>>>(Cat_dst, label, w,
                              W_agg, b_agg, w_lin, b_lin,
                              W1, b1, W2, b2, W3, b3,
                              out, Nd, write_label);
}

// round 6
// speedup vs baseline: 1.7515x; 1.0715x over previous
#include <cuda_runtime.h>
#include <cuda_fp16.h>
#include <math.h>

typedef unsigned long long ull;

// ---------------- static scratch (no allocs) --------------------------------
#define NSMAX 1000000
#define NDMAX 100000
#define EMAX  3200000

__device__ int    g_deg[NDMAX];
__device__ int    g_rowptr[NDMAX + 1];
__device__ int    g_cursor[NDMAX];
__device__ int    g_look[1024];          // lookback state: bits28-29 state, low 28 value
__device__ int    g_perm[EMAX];
__device__ __half g_hsrc[NSMAX * 32];    // [Ns][d][mean,max] interleaved half2 pairs
__device__ float  g_tmp[NDMAX * 128];    // [Nd][k*64 + stat*16 + d]

#define LOG_AVG 3.4965075614664802f      // log(33.0)

// ---------------- f32x2 helpers ---------------------------------------------
__device__ __forceinline__ void fma2(ull& acc, ull a, ull b) {
    asm("fma.rn.f32x2 %0, %1, %2, %0;" : "+l"(acc) : "l"(a), "l"(b));
}
__device__ __forceinline__ float hsum2(ull v) {
    float lo, hi;
    asm("mov.b64 {%0,%1}, %2;" : "=f"(lo), "=f"(hi) : "l"(v));
    return lo + hi;
}

// ---------------- k_pre: reset lookback + histogram + h_src -----------------
__global__ __launch_bounds__(256) void k_pre(
    const int* __restrict__ Cat_src, const int* __restrict__ dst_ids,
    const float* __restrict__ w, int E, int Ns)
{
    int gtid = blockIdx.x * blockDim.x + threadIdx.x;
    int gstride = gridDim.x * blockDim.x;

    if (gtid < 1024) g_look[gtid] = 0;

    // histogram (int4 edge loads)
    int e4 = E >> 2;
    for (int i = gtid; i < e4; i += gstride) {
        int4 dd = ((const int4*)dst_ids)[i];
        atomicAdd(&g_deg[dd.x], 1);
        atomicAdd(&g_deg[dd.y], 1);
        atomicAdd(&g_deg[dd.z], 1);
        atomicAdd(&g_deg[dd.w], 1);
    }
    if (gtid < (E & 3)) atomicAdd(&g_deg[dst_ids[e4 * 4 + gtid]], 1);

    // h_src: 2 nodes per warp (half-warp each), interleaved (mean,max) layout
    int lane = threadIdx.x & 31;
    int half = lane >> 4;
    int j = lane & 15;
    __half2* H = (__half2*)g_hsrc;
    int gw = gtid >> 5;
    int wstride = gstride >> 5;
    int npairs = (Ns + 1) >> 1;
    for (int p = gw; p < npairs; p += wstride) {
        int n = p * 2 + half;
        if (n < Ns) {
            int4 c = ((const int4*)Cat_src)[n];      // broadcast within half
            float v0 = w[c.x * 16 + j];
            float v1 = w[c.y * 16 + j];
            float v2 = w[c.z * 16 + j];
            float v3 = w[c.w * 16 + j];
            float me = (v0 + v1 + v2 + v3) * 0.25f;
            float ma = fmaxf(fmaxf(v0, v1), fmaxf(v2, v3));
            H[n * 16 + j] = __floats2half2_rn(me, ma);
        }
    }
}

// ---------------- k_scan: fused scan + fix (decoupled lookback) -------------
__global__ __launch_bounds__(512) void k_scan(int nd, int E) {
    int b = blockIdx.x;
    int tid = threadIdx.x;
    int n = b * 512 + tid;
    int v = (n < nd) ? g_deg[n] : 0;
    int lane = tid & 31, wid = tid >> 5;

    // block inclusive scan
    int x = v;
#pragma unroll
    for (int o = 1; o < 32; o <<= 1) {
        int y = __shfl_up_sync(0xffffffffu, x, o);
        if (lane >= o) x += y;
    }
    __shared__ int ws[16];
    __shared__ int s_pre;
    if (lane == 31) ws[wid] = x;
    __syncthreads();
    if (wid == 0) {
        int s = (lane < 16) ? ws[lane] : 0;
#pragma unroll
        for (int o = 1; o < 16; o <<= 1) {
            int y = __shfl_up_sync(0xffffffffu, s, o);
            if (lane >= o) s += y;
        }
        if (lane < 16) ws[lane] = s;
    }
    __syncthreads();
    int off = wid ? ws[wid - 1] : 0;
    int incl = x + off;
    int total = ws[15];

    // decoupled lookback (warp 0)
    if (wid == 0) {
        if (b == 0) {
            if (lane == 0) {
                atomicExch(&g_look[0], (2 << 28) | total);
                s_pre = 0;
            }
        } else {
            if (lane == 0) atomicExch(&g_look[b], (1 << 28) | total);
            __syncwarp();
            int pre = 0;
            int idx = b - 1;
            while (true) {
                int i = idx - lane;
                int e;
                if (i >= 0) {
                    do { e = atomicAdd(&g_look[i], 0); } while ((e >> 28) == 0);
                } else {
                    e = (2 << 28);
                }
                unsigned pf = __ballot_sync(0xffffffffu, (e >> 28) == 2);
                int val = e & 0x0FFFFFFF;
                if (pf) {
                    int L = __ffs(pf) - 1;      // nearest prefix (largest block idx)
                    int contrib = (lane <= L) ? val : 0;
#pragma unroll
                    for (int o = 16; o; o >>= 1) contrib += __shfl_xor_sync(0xffffffffu, contrib, o);
                    pre += contrib;
                    break;
                } else {
                    int contrib = val;
#pragma unroll
                    for (int o = 16; o; o >>= 1) contrib += __shfl_xor_sync(0xffffffffu, contrib, o);
                    pre += contrib;
                    idx -= 32;
                }
            }
            if (lane == 0) {
                atomicExch(&g_look[b], (2 << 28) | (pre + total));
                s_pre = pre;
            }
        }
    }
    __syncthreads();
    int pre = s_pre;

    if (n < nd) {
        int r = (incl - v) + pre;
        g_rowptr[n] = r;
        g_cursor[n] = r;
        g_deg[n] = 0;                    // ready for next call's histogram
        if (n == 0) g_rowptr[nd] = E;
    }
}

// ---------------- k_scatter -------------------------------------------------
__global__ __launch_bounds__(256) void k_scatter(
    const int* __restrict__ src, const int* __restrict__ dst, int E)
{
    int i = blockIdx.x * blockDim.x + threadIdx.x;
    int e4 = E >> 2;
    if (i < e4) {
        int4 s = ((const int4*)src)[i];
        int4 d = ((const int4*)dst)[i];
        g_perm[atomicAdd(&g_cursor[d.x], 1)] = s.x;
        g_perm[atomicAdd(&g_cursor[d.y], 1)] = s.y;
        g_perm[atomicAdd(&g_cursor[d.z], 1)] = s.z;
        g_perm[atomicAdd(&g_cursor[d.w], 1)] = s.w;
    }
    if (i < (E & 3)) {
        int e = e4 * 4 + i;
        g_perm[atomicAdd(&g_cursor[dst[e]], 1)] = src[e];
    }
}

// ---------------- k_agg: 2 dst-nodes per warp, half2 (mean,max) pairs -------
__global__ __launch_bounds__(256) void k_agg(int Nd)
{
    int lane = threadIdx.x & 31;
    int half = lane >> 4;
    int j = lane & 15;                   // d channel
    int n = (((blockIdx.x * 256 + threadIdx.x) >> 5) << 1) + half;
    if (n >= Nd) return;

    int base = g_rowptr[n], end = g_rowptr[n + 1];
    const __half2* H = (const __half2*)g_hsrc;

    float s0f = 0.f, s1f = 0.f, q0 = 0.f, q1 = 0.f;
    float mn0 = 3.4e38f, mn1 = 3.4e38f, mx0 = -3.4e38f, mx1 = -3.4e38f;

    int i = base;
    for (; i + 1 < end; i += 2) {
        int e0 = g_perm[i];
        int e1 = g_perm[i + 1];
        float2 a = __half22float2(H[e0 * 16 + j]);
        float2 b = __half22float2(H[e1 * 16 + j]);
        s0f += a.x + b.x;  s1f += a.y + b.y;
        q0 = fmaf(a.x, a.x, q0); q0 = fmaf(b.x, b.x, q0);
        q1 = fmaf(a.y, a.y, q1); q1 = fmaf(b.y, b.y, q1);
        mn0 = fminf(mn0, fminf(a.x, b.x)); mn1 = fminf(mn1, fminf(a.y, b.y));
        mx0 = fmaxf(mx0, fmaxf(a.x, b.x)); mx1 = fmaxf(mx1, fmaxf(a.y, b.y));
    }
    if (i < end) {
        int e0 = g_perm[i];
        float2 a = __half22float2(H[e0 * 16 + j]);
        s0f += a.x; s1f += a.y;
        q0 = fmaf(a.x, a.x, q0); q1 = fmaf(a.y, a.y, q1);
        mn0 = fminf(mn0, a.x); mn1 = fminf(mn1, a.y);
        mx0 = fmaxf(mx0, a.x); mx1 = fmaxf(mx1, a.y);
    }

    float deg = (float)(end - base);
    float inv = 1.f / fmaxf(deg, 1.f);
    bool has = deg > 0.f;
    float mean0 = s0f * inv, mean1 = s1f * inv;
    float sd0 = sqrtf(fmaxf(q0 * inv - mean0 * mean0, 0.f) + 1e-5f);
    float sd1 = sqrtf(fmaxf(q1 * inv - mean1 * mean1, 0.f) + 1e-5f);
    if (!has) { mn0 = mn1 = mx0 = mx1 = 0.f; }

    // channel 0 (mean-emb) -> k=0 block; channel 1 (max-emb) -> k=1 block
    float* t = g_tmp + n * 128;
    t[j]       = mean0;  t[16 + j]  = mn0;  t[32 + j]  = mx0;  t[48 + j]  = sd0;
    t[64 + j]  = mean1;  t[80 + j]  = mn1;  t[96 + j]  = mx1;  t[112 + j] = sd1;
}

// ---------------- k_mlp: 128-node tiles, 8 nodes/warp, f32x2 + LDS.128 ------
// Weight layouts (floats), pair-interleaved over feature index f:
//   W_agg: [k](3088) [sec](1024) [f2]*32 + d*2 + (f&1)
//   W1:    [f2]*128 + o*2 + (f&1)
//   W2:    [f2]*64  + o*2 + (f&1)
#define SM2_WAGG  0        // 6176
#define SM2_W1    6176     // 6144
#define SM2_W2    12320    // 2048
#define SM2_BAGG  14368    // 32
#define SM2_B1    14400    // 64
#define SM2_B2    14464    // 32
#define SM2_W3    14496    // 32
#define SM2_WLIN  14528    // 96
#define SM2_MISC  14624    // 2
#define SM2_AMP   14628    // 128
#define SM2_ATT   14756    // 128
#define SM2_CD    14884    // 512 ints
#define SM2_TMP   15396    // 128 nodes * 136 (k pitch 68); aliased by h1 (pitch 68)
#define SM2_X     32804    // 128 nodes * 100
#define SM2_TOTAL (32804 + 128 * 100)   // 45604 floats = 182416 B

__global__ __launch_bounds__(512, 1) void k_mlp(
    const int* __restrict__ Cat_dst, const int* __restrict__ label,
    const float* __restrict__ w,
    const float* __restrict__ W_agg, const float* __restrict__ b_agg,
    const float* __restrict__ w_lin, const float* __restrict__ b_lin,
    const float* __restrict__ W1, const float* __restrict__ b1,
    const float* __restrict__ W2, const float* __restrict__ b2,
    const float* __restrict__ W3, const float* __restrict__ b3,
    float* __restrict__ out, int Nd, int write_label)
{
    extern __shared__ float sm[];
    int tid = threadIdx.x;
    int lane = tid & 31, warp = tid >> 5;
    int k = lane >> 4, d = lane & 15;
    int* cd_s = (int*)(sm + SM2_CD);

    // ---- stage weights (pair-interleaved) ----
    for (int i = tid; i < 6144; i += 512) {
        int kk = i / 3072;
        int r = i - kk * 3072;
        int sec = r >> 10;
        int rr = r & 1023;
        int ff = rr >> 4, dd = rr & 15;
        sm[SM2_WAGG + kk * 3088 + sec * 1024 + (ff >> 1) * 32 + dd * 2 + (ff & 1)] = W_agg[i];
        int f1 = i >> 6, o1 = i & 63;
        sm[SM2_W1 + (f1 >> 1) * 128 + o1 * 2 + (f1 & 1)] = W1[i];
    }
    for (int i = tid; i < 2048; i += 512) {
        int f2_ = i >> 5, o2 = i & 31;
        sm[SM2_W2 + (f2_ >> 1) * 64 + o2 * 2 + (f2_ & 1)] = W2[i];
    }
    if (tid < 32) { sm[SM2_BAGG + tid] = b_agg[tid]; sm[SM2_B2 + tid] = b2[tid]; sm[SM2_W3 + tid] = W3[tid]; }
    if (tid >= 32 && tid < 96) sm[SM2_B1 + tid - 32] = b1[tid - 32];
    if (tid >= 96 && tid < 192) sm[SM2_WLIN + tid - 96] = w_lin[tid - 96];
    if (tid == 192) { sm[SM2_MISC + 0] = b_lin[0]; sm[SM2_MISC + 1] = b3[0]; }
    __syncthreads();

    int ntiles = (Nd + 127) >> 7;
    for (int t = blockIdx.x; t < ntiles; t += gridDim.x) {
        int n0 = t << 7;
        __syncthreads();   // smem reuse guard

        // ---- P1: stage tmp (128 nodes x 128), Cat_dst, amp/att ----
#pragma unroll
        for (int i = 0; i < 32; i++) {
            int g = tid + i * 512;
            int node = g >> 7, f = g & 127;
            int n = n0 + node; if (n >= Nd) n = Nd - 1;
            sm[SM2_TMP + node * 136 + (f >> 6) * 68 + (f & 63)] = g_tmp[n * 128 + f];
        }
        {
            int n = n0 + (tid >> 2); if (n >= Nd) n = Nd - 1;
            cd_s[tid] = Cat_dst[n * 4 + (tid & 3)];
        }
        if (tid < 128) {
            int n = n0 + tid; if (n >= Nd) n = Nd - 1;
            float deg = (float)(g_rowptr[n + 1] - g_rowptr[n]);
            float logd = logf(deg + 1.f);
            sm[SM2_AMP + tid] = logd * (1.f / LOG_AVG);
            sm[SM2_ATT + tid] = (logd > 0.f) ? (LOG_AVG / fmaxf(logd, 1e-5f)) : 0.f;
        }
        __syncthreads();

        // ---- P3: dst-embedding gathers into x[0..63] ----
#pragma unroll
        for (int i = 0; i < 16; i++) {
            int g = tid + i * 512;
            int node = g >> 6, j = g & 63;
            int ci = cd_s[node * 4 + (j >> 4)];
            sm[SM2_X + node * 100 + j] = w[ci * 16 + (j & 15)];
        }

        // ---- P2: PNA einsum (f32x2), 8 nodes per warp ----
        {
            int nw = warp * 8;
            const ull* W0 = (const ull*)(sm + SM2_WAGG + k * 3088) + d;   // +f2*16; sections +512,+1024
            const ulonglong2* T[8];
#pragma unroll
            for (int j = 0; j < 8; j++)
                T[j] = (const ulonglong2*)(sm + SM2_TMP + (nw + j) * 136 + k * 68);
            ull a0[8], a1[8], a2[8];
#pragma unroll
            for (int j = 0; j < 8; j++) { a0[j] = 0; a1[j] = 0; a2[j] = 0; }
#pragma unroll 2
            for (int f4 = 0; f4 < 16; f4++) {
                ull w00 = W0[(2 * f4) * 16],        w01 = W0[(2 * f4 + 1) * 16];
                ull w10 = W0[512 + (2 * f4) * 16],  w11 = W0[512 + (2 * f4 + 1) * 16];
                ull w20 = W0[1024 + (2 * f4) * 16], w21 = W0[1024 + (2 * f4 + 1) * 16];
#pragma unroll
                for (int j = 0; j < 8; j++) {
                    ulonglong2 v = T[j][f4];
                    fma2(a0[j], v.x, w00); fma2(a0[j], v.y, w01);
                    fma2(a1[j], v.x, w10); fma2(a1[j], v.y, w11);
                    fma2(a2[j], v.x, w20); fma2(a2[j], v.y, w21);
                }
            }
            float bg = sm[SM2_BAGG + lane];
#pragma unroll
            for (int j = 0; j < 8; j++) {
                int node = nw + j;
                sm[SM2_X + node * 100 + 64 + lane] =
                    bg + hsum2(a0[j]) + sm[SM2_AMP + node] * hsum2(a1[j])
                       + sm[SM2_ATT + node] * hsum2(a2[j]);
            }
        }
        __syncthreads();   // x complete; tmp dead -> h1 alias safe

        // ---- P4: h1 = relu(x @ W1 + b1), f32x2 ----
        float* h1_s = sm + SM2_TMP;   // alias, node pitch 68
        {
            int nw = warp * 8;
            const ull* W1a = (const ull*)(sm + SM2_W1) + lane;        // +f2*64; +32 for hi half
            const ulonglong2* X[8];
#pragma unroll
            for (int j = 0; j < 8; j++)
                X[j] = (const ulonglong2*)(sm + SM2_X + (nw + j) * 100);
            ull h0[8], h1r[8];
#pragma unroll
            for (int j = 0; j < 8; j++) { h0[j] = 0; h1r[j] = 0; }
#pragma unroll 2
            for (int f4 = 0; f4 < 24; f4++) {
                ull wa0 = W1a[(2 * f4) * 64],      wa1 = W1a[(2 * f4 + 1) * 64];
                ull wb0 = W1a[32 + (2 * f4) * 64], wb1 = W1a[32 + (2 * f4 + 1) * 64];
#pragma unroll
                for (int j = 0; j < 8; j++) {
                    ulonglong2 v = X[j][f4];
                    fma2(h0[j], v.x, wa0);  fma2(h0[j], v.y, wa1);
                    fma2(h1r[j], v.x, wb0); fma2(h1r[j], v.y, wb1);
                }
            }
            float b1a = sm[SM2_B1 + lane], b1b = sm[SM2_B1 + 32 + lane];
#pragma unroll
            for (int j = 0; j < 8; j++) {
                h1_s[(nw + j) * 68 + lane]      = fmaxf(hsum2(h0[j]) + b1a, 0.f);
                h1_s[(nw + j) * 68 + 32 + lane] = fmaxf(hsum2(h1r[j]) + b1b, 0.f);
            }
        }
        __syncwarp();

        // ---- P6: h2 = relu(h1 @ W2 + b2); deep partial = h2 * W3[lane] ----
        float gdeep[8];
        {
            int nw = warp * 8;
            const ull* W2p = (const ull*)(sm + SM2_W2) + lane;        // +f2*32
            const ulonglong2* Hh[8];
#pragma unroll
            for (int j = 0; j < 8; j++)
                Hh[j] = (const ulonglong2*)(h1_s + (nw + j) * 68);
            ull a[8];
#pragma unroll
            for (int j = 0; j < 8; j++) a[j] = 0;
#pragma unroll 2
            for (int f4 = 0; f4 < 16; f4++) {
                ull wv0 = W2p[(2 * f4) * 32], wv1 = W2p[(2 * f4 + 1) * 32];
#pragma unroll
                for (int j = 0; j < 8; j++) {
                    ulonglong2 v = Hh[j][f4];
                    fma2(a[j], v.x, wv0); fma2(a[j], v.y, wv1);
                }
            }
            float b2v = sm[SM2_B2 + lane];
            float w3v = sm[SM2_W3 + lane];
#pragma unroll
            for (int j = 0; j < 8; j++)
                gdeep[j] = fmaxf(hsum2(a[j]) + b2v, 0.f) * w3v;
        }

        // ---- P7: lin + fm per node, reduce, output ----
        {
            float wl0 = sm[SM2_WLIN + lane], wl1 = sm[SM2_WLIN + 32 + lane], wl2 = sm[SM2_WLIN + 64 + lane];
            float bl = sm[SM2_MISC + 0] + sm[SM2_MISC + 1];
#pragma unroll
            for (int j = 0; j < 8; j++) {
                int node = warp * 8 + j;
                const float* xs = sm + SM2_X + node * 100;
                float e0 = xs[lane], e1 = xs[32 + lane], e2 = xs[64 + lane];
                float lin_p = e0 * wl0 + e1 * wl1 + e2 * wl2;
                float tsum = e0 + e1 + e2;
                float qsum = e0 * e0 + e1 * e1 + e2 * e2;
                float s = tsum + __shfl_xor_sync(0xffffffffu, tsum, 16);
                float qs = qsum + __shfl_xor_sync(0xffffffffu, qsum, 16);
                float r = lin_p + gdeep[j] + 0.25f * (s * s - qs);
#pragma unroll
                for (int o = 16; o; o >>= 1)
                    r += __shfl_xor_sync(0xffffffffu, r, o);
                int n = n0 + node;
                if (lane == 0 && n < Nd) {
                    float z = r + bl;
                    out[n] = 1.f / (1.f + expf(-z));
                    if (write_label) out[Nd + n] = (float)label[n];
                }
            }
        }
    }
}

// ---------------- launch ----------------------------------------------------
extern "C" void kernel_launch(void* const* d_in, const int* in_sizes, int n_in,
                              void* d_out, int out_size) {
    const int*   Cat_src = (const int*)  d_in[0];
    const int*   Cat_dst = (const int*)  d_in[1];
    const int*   src_ids = (const int*)  d_in[2];
    const int*   dst_ids = (const int*)  d_in[3];
    const int*   label   = (const int*)  d_in[4];
    const float* w       = (const float*)d_in[5];
    const float* W_agg   = (const float*)d_in[6];
    const float* b_agg   = (const float*)d_in[7];
    const float* w_lin   = (const float*)d_in[8];
    const float* b_lin   = (const float*)d_in[9];
    const float* W1      = (const float*)d_in[10];
    const float* b1      = (const float*)d_in[11];
    const float* W2      = (const float*)d_in[12];
    const float* b2      = (const float*)d_in[13];
    const float* W3      = (const float*)d_in[14];
    const float* b3      = (const float*)d_in[15];

    int Ns = in_sizes[0] / 4;
    int Nd = in_sizes[1] / 4;
    int E  = in_sizes[2];
    float* out = (float*)d_out;
    int write_label = (out_size >= 2 * Nd) ? 1 : 0;

    // 0: lookback reset + histogram + h_src
    k_pre<<<2048, 256>>>(Cat_src, dst_ids, w, E, Ns);
    // 1: fused CSR scan + fix (decoupled lookback)
    int nb = (Nd + 511) / 512;
    k_scan<<<nb, 512>>>(Nd, E);
    // 2: edge permutation
    int e4 = (E + 3) / 4;
    k_scatter<<<(e4 + 255) / 256, 256>>>(src_ids, dst_ids, E);
    // 3: segment reduction (profiled slot)
    k_agg<<<(Nd + 15) / 16, 256>>>(Nd);
    // 4: einsum + DeepFM (f32x2, 128-node tiles)
    int ntiles = (Nd + 127) >> 7;
    size_t smem = SM2_TOTAL * sizeof(float);
    cudaFuncSetAttribute(k_mlp, cudaFuncAttributeMaxDynamicSharedMemorySize, (int)smem);
    k_mlp<<<ntiles, 512, smem>>>(Cat_dst, label, w,
                                 W_agg, b_agg, w_lin, b_lin,
                                 W1, b1, W2, b2, W3, b3,
                                 out, Nd, write_label);
}

// round 7
// speedup vs baseline: 1.7865x; 1.0200x over previous
#include <cuda_runtime.h>
#include <cuda_fp16.h>
#include <math.h>

typedef unsigned long long ull;

// ---------------- static scratch (no allocs) --------------------------------
#define NSMAX 1000000
#define NDMAX 100000
#define EMAX  3200000

__device__ int    g_deg[NDMAX];
__device__ int    g_rowptr[NDMAX + 1];
__device__ int    g_cursor[NDMAX];
__device__ int    g_look[1024];          // lookback state: bits28-29 state, low 28 value
__device__ int    g_perm[EMAX];
__device__ __half g_hsrc[NSMAX * 32];    // [Ns][d][mean,max] interleaved half2 pairs
__device__ float  g_tmp[NDMAX * 128];    // [Nd][k*64 + stat*16 + d]

#define LOG_AVG 3.4965075614664802f      // log(33.0)

// ---------------- f32x2 helpers ---------------------------------------------
__device__ __forceinline__ void fma2(ull& acc, ull a, ull b) {
    asm("fma.rn.f32x2 %0, %1, %2, %0;" : "+l"(acc) : "l"(a), "l"(b));
}
__device__ __forceinline__ float hsum2(ull v) {
    float lo, hi;
    asm("mov.b64 {%0,%1}, %2;" : "=f"(lo), "=f"(hi) : "l"(v));
    return lo + hi;
}

// ---------------- k_pre: reset lookback + histogram + h_src -----------------
__global__ __launch_bounds__(256) void k_pre(
    const int* __restrict__ Cat_src, const int* __restrict__ dst_ids,
    const float* __restrict__ w, int E, int Ns)
{
    int gtid = blockIdx.x * blockDim.x + threadIdx.x;
    int gstride = gridDim.x * blockDim.x;

    if (gtid < 1024) g_look[gtid] = 0;

    // histogram (int4 edge loads, streaming)
    int e4 = E >> 2;
    for (int i = gtid; i < e4; i += gstride) {
        int4 dd = __ldcs(&((const int4*)dst_ids)[i]);
        atomicAdd(&g_deg[dd.x], 1);
        atomicAdd(&g_deg[dd.y], 1);
        atomicAdd(&g_deg[dd.z], 1);
        atomicAdd(&g_deg[dd.w], 1);
    }
    if (gtid < (E & 3)) atomicAdd(&g_deg[dst_ids[e4 * 4 + gtid]], 1);

    // h_src: 4 nodes per warp-iteration (2 per half-warp), (mean,max) half2 layout
    int lane = threadIdx.x & 31;
    int half = lane >> 4;
    int j = lane & 15;
    __half2* H = (__half2*)g_hsrc;
    int gw = gtid >> 5;
    int wstride = gstride >> 5;
    int nquads = (Ns + 3) >> 2;
    for (int q = gw; q < nquads; q += wstride) {
        int nA = q * 4 + half;
        int nB = nA + 2;
        if (nA < Ns) {
            int4 cA = ((const int4*)Cat_src)[nA];
            int4 cB = (nB < Ns) ? ((const int4*)Cat_src)[nB] : cA;
            float a0 = w[cA.x * 16 + j], a1 = w[cA.y * 16 + j];
            float a2 = w[cA.z * 16 + j], a3 = w[cA.w * 16 + j];
            float b0 = w[cB.x * 16 + j], b1 = w[cB.y * 16 + j];
            float b2 = w[cB.z * 16 + j], b3 = w[cB.w * 16 + j];
            float meA = (a0 + a1 + a2 + a3) * 0.25f;
            float maA = fmaxf(fmaxf(a0, a1), fmaxf(a2, a3));
            float meB = (b0 + b1 + b2 + b3) * 0.25f;
            float maB = fmaxf(fmaxf(b0, b1), fmaxf(b2, b3));
            H[nA * 16 + j] = __floats2half2_rn(meA, maA);
            if (nB < Ns) H[nB * 16 + j] = __floats2half2_rn(meB, maB);
        }
    }
}

// ---------------- k_scan: fused scan + fix (decoupled lookback) -------------
__global__ __launch_bounds__(512) void k_scan(int nd, int E) {
    int b = blockIdx.x;
    int tid = threadIdx.x;
    int n = b * 512 + tid;
    int v = (n < nd) ? g_deg[n] : 0;
    int lane = tid & 31, wid = tid >> 5;

    int x = v;
#pragma unroll
    for (int o = 1; o < 32; o <<= 1) {
        int y = __shfl_up_sync(0xffffffffu, x, o);
        if (lane >= o) x += y;
    }
    __shared__ int ws[16];
    __shared__ int s_pre;
    if (lane == 31) ws[wid] = x;
    __syncthreads();
    if (wid == 0) {
        int s = (lane < 16) ? ws[lane] : 0;
#pragma unroll
        for (int o = 1; o < 16; o <<= 1) {
            int y = __shfl_up_sync(0xffffffffu, s, o);
            if (lane >= o) s += y;
        }
        if (lane < 16) ws[lane] = s;
    }
    __syncthreads();
    int off = wid ? ws[wid - 1] : 0;
    int incl = x + off;
    int total = ws[15];

    if (wid == 0) {
        if (b == 0) {
            if (lane == 0) {
                atomicExch(&g_look[0], (2 << 28) | total);
                s_pre = 0;
            }
        } else {
            if (lane == 0) atomicExch(&g_look[b], (1 << 28) | total);
            __syncwarp();
            int pre = 0;
            int idx = b - 1;
            while (true) {
                int i = idx - lane;
                int e;
                if (i >= 0) {
                    do { e = atomicAdd(&g_look[i], 0); } while ((e >> 28) == 0);
                } else {
                    e = (2 << 28);
                }
                unsigned pf = __ballot_sync(0xffffffffu, (e >> 28) == 2);
                int val = e & 0x0FFFFFFF;
                if (pf) {
                    int L = __ffs(pf) - 1;
                    int contrib = (lane <= L) ? val : 0;
#pragma unroll
                    for (int o = 16; o; o >>= 1) contrib += __shfl_xor_sync(0xffffffffu, contrib, o);
                    pre += contrib;
                    break;
                } else {
                    int contrib = val;
#pragma unroll
                    for (int o = 16; o; o >>= 1) contrib += __shfl_xor_sync(0xffffffffu, contrib, o);
                    pre += contrib;
                    idx -= 32;
                }
            }
            if (lane == 0) {
                atomicExch(&g_look[b], (2 << 28) | (pre + total));
                s_pre = pre;
            }
        }
    }
    __syncthreads();
    int pre = s_pre;

    if (n < nd) {
        int r = (incl - v) + pre;
        g_rowptr[n] = r;
        g_cursor[n] = r;
        g_deg[n] = 0;
        if (n == 0) g_rowptr[nd] = E;
    }
}

// ---------------- k_scatter: 8 edges per thread ------------------------------
__global__ __launch_bounds__(256) void k_scatter(
    const int* __restrict__ src, const int* __restrict__ dst, int E)
{
    int e4 = E >> 2;
#pragma unroll
    for (int u = 0; u < 2; u++) {
        int i = blockIdx.x * 512 + u * 256 + threadIdx.x;
        if (i < e4) {
            int4 s = __ldcs(&((const int4*)src)[i]);
            int4 d = __ldcs(&((const int4*)dst)[i]);
            g_perm[atomicAdd(&g_cursor[d.x], 1)] = s.x;
            g_perm[atomicAdd(&g_cursor[d.y], 1)] = s.y;
            g_perm[atomicAdd(&g_cursor[d.z], 1)] = s.z;
            g_perm[atomicAdd(&g_cursor[d.w], 1)] = s.w;
        }
    }
    int t = blockIdx.x * 512 + threadIdx.x;
    if (t < (E & 3)) {
        int e = e4 * 4 + t;
        g_perm[atomicAdd(&g_cursor[dst[e]], 1)] = src[e];
    }
}

// ---------------- k_agg: 2 dst-nodes per warp, unroll-4, half2 pairs --------
__global__ __launch_bounds__(256) void k_agg(int Nd)
{
    int lane = threadIdx.x & 31;
    int half = lane >> 4;
    int j = lane & 15;                   // d channel
    int n = (((blockIdx.x * 256 + threadIdx.x) >> 5) << 1) + half;
    if (n >= Nd) return;

    int base = g_rowptr[n], end = g_rowptr[n + 1];
    const __half2* H = (const __half2*)g_hsrc;

    float s0f = 0.f, s1f = 0.f, q0 = 0.f, q1 = 0.f;
    float mn0 = 3.4e38f, mn1 = 3.4e38f, mx0 = -3.4e38f, mx1 = -3.4e38f;

    int i = base;
    for (; i + 3 < end; i += 4) {
        int e0 = __ldcs(&g_perm[i]);
        int e1 = __ldcs(&g_perm[i + 1]);
        int e2 = __ldcs(&g_perm[i + 2]);
        int e3 = __ldcs(&g_perm[i + 3]);
        float2 a = __half22float2(H[e0 * 16 + j]);
        float2 b = __half22float2(H[e1 * 16 + j]);
        float2 c = __half22float2(H[e2 * 16 + j]);
        float2 e = __half22float2(H[e3 * 16 + j]);
        s0f += (a.x + b.x) + (c.x + e.x);
        s1f += (a.y + b.y) + (c.y + e.y);
        q0 = fmaf(a.x, a.x, q0); q0 = fmaf(b.x, b.x, q0);
        q0 = fmaf(c.x, c.x, q0); q0 = fmaf(e.x, e.x, q0);
        q1 = fmaf(a.y, a.y, q1); q1 = fmaf(b.y, b.y, q1);
        q1 = fmaf(c.y, c.y, q1); q1 = fmaf(e.y, e.y, q1);
        mn0 = fminf(mn0, fminf(fminf(a.x, b.x), fminf(c.x, e.x)));
        mn1 = fminf(mn1, fminf(fminf(a.y, b.y), fminf(c.y, e.y)));
        mx0 = fmaxf(mx0, fmaxf(fmaxf(a.x, b.x), fmaxf(c.x, e.x)));
        mx1 = fmaxf(mx1, fmaxf(fmaxf(a.y, b.y), fmaxf(c.y, e.y)));
    }
    for (; i < end; i++) {
        int e0 = __ldcs(&g_perm[i]);
        float2 a = __half22float2(H[e0 * 16 + j]);
        s0f += a.x; s1f += a.y;
        q0 = fmaf(a.x, a.x, q0); q1 = fmaf(a.y, a.y, q1);
        mn0 = fminf(mn0, a.x); mn1 = fminf(mn1, a.y);
        mx0 = fmaxf(mx0, a.x); mx1 = fmaxf(mx1, a.y);
    }

    float deg = (float)(end - base);
    float inv = 1.f / fmaxf(deg, 1.f);
    bool has = deg > 0.f;
    float mean0 = s0f * inv, mean1 = s1f * inv;
    float sd0 = sqrtf(fmaxf(q0 * inv - mean0 * mean0, 0.f) + 1e-5f);
    float sd1 = sqrtf(fmaxf(q1 * inv - mean1 * mean1, 0.f) + 1e-5f);
    if (!has) { mn0 = mn1 = mx0 = mx1 = 0.f; }

    float* t = g_tmp + n * 128;
    t[j]       = mean0;  t[16 + j]  = mn0;  t[32 + j]  = mx0;  t[48 + j]  = sd0;
    t[64 + j]  = mean1;  t[80 + j]  = mn1;  t[96 + j]  = mx1;  t[112 + j] = sd1;
}

// ---------------- k_mlp: 128-node tiles, 8 nodes/warp, f32x2 + LDS.128 ------
#define SM2_WAGG  0        // 6176
#define SM2_W1    6176     // 6144
#define SM2_W2    12320    // 2048
#define SM2_BAGG  14368    // 32
#define SM2_B1    14400    // 64
#define SM2_B2    14464    // 32
#define SM2_W3    14496    // 32
#define SM2_WLIN  14528    // 96
#define SM2_MISC  14624    // 2
#define SM2_AMP   14628    // 128
#define SM2_ATT   14756    // 128
#define SM2_CD    14884    // 512 ints
#define SM2_TMP   15396    // 128 nodes * 136 (k pitch 68); aliased by h1 (pitch 68)
#define SM2_X     32804    // 128 nodes * 100
#define SM2_TOTAL (32804 + 128 * 100)   // 45604 floats = 182416 B

__global__ __launch_bounds__(512, 1) void k_mlp(
    const int* __restrict__ Cat_dst, const int* __restrict__ label,
    const float* __restrict__ w,
    const float* __restrict__ W_agg, const float* __restrict__ b_agg,
    const float* __restrict__ w_lin, const float* __restrict__ b_lin,
    const float* __restrict__ W1, const float* __restrict__ b1,
    const float* __restrict__ W2, const float* __restrict__ b2,
    const float* __restrict__ W3, const float* __restrict__ b3,
    float* __restrict__ out, int Nd, int write_label)
{
    extern __shared__ float sm[];
    int tid = threadIdx.x;
    int lane = tid & 31, warp = tid >> 5;
    int k = lane >> 4, d = lane & 15;
    int* cd_s = (int*)(sm + SM2_CD);

    for (int i = tid; i < 6144; i += 512) {
        int kk = i / 3072;
        int r = i - kk * 3072;
        int sec = r >> 10;
        int rr = r & 1023;
        int ff = rr >> 4, dd = rr & 15;
        sm[SM2_WAGG + kk * 3088 + sec * 1024 + (ff >> 1) * 32 + dd * 2 + (ff & 1)] = W_agg[i];
        int f1 = i >> 6, o1 = i & 63;
        sm[SM2_W1 + (f1 >> 1) * 128 + o1 * 2 + (f1 & 1)] = W1[i];
    }
    for (int i = tid; i < 2048; i += 512) {
        int f2_ = i >> 5, o2 = i & 31;
        sm[SM2_W2 + (f2_ >> 1) * 64 + o2 * 2 + (f2_ & 1)] = W2[i];
    }
    if (tid < 32) { sm[SM2_BAGG + tid] = b_agg[tid]; sm[SM2_B2 + tid] = b2[tid]; sm[SM2_W3 + tid] = W3[tid]; }
    if (tid >= 32 && tid < 96) sm[SM2_B1 + tid - 32] = b1[tid - 32];
    if (tid >= 96 && tid < 192) sm[SM2_WLIN + tid - 96] = w_lin[tid - 96];
    if (tid == 192) { sm[SM2_MISC + 0] = b_lin[0]; sm[SM2_MISC + 1] = b3[0]; }
    __syncthreads();

    int ntiles = (Nd + 127) >> 7;
    for (int t = blockIdx.x; t < ntiles; t += gridDim.x) {
        int n0 = t << 7;
        __syncthreads();

        // ---- P1: stage tmp (128 nodes x 128), Cat_dst, amp/att ----
#pragma unroll
        for (int i = 0; i < 32; i++) {
            int g = tid + i * 512;
            int node = g >> 7, f = g & 127;
            int n = n0 + node; if (n >= Nd) n = Nd - 1;
            sm[SM2_TMP + node * 136 + (f >> 6) * 68 + (f & 63)] = __ldcs(&g_tmp[n * 128 + f]);
        }
        {
            int n = n0 + (tid >> 2); if (n >= Nd) n = Nd - 1;
            cd_s[tid] = Cat_dst[n * 4 + (tid & 3)];
        }
        if (tid < 128) {
            int n = n0 + tid; if (n >= Nd) n = Nd - 1;
            float deg = (float)(g_rowptr[n + 1] - g_rowptr[n]);
            float logd = logf(deg + 1.f);
            sm[SM2_AMP + tid] = logd * (1.f / LOG_AVG);
            sm[SM2_ATT + tid] = (logd > 0.f) ? (LOG_AVG / fmaxf(logd, 1e-5f)) : 0.f;
        }
        __syncthreads();

        // ---- P3: dst-embedding gathers into x[0..63] ----
#pragma unroll
        for (int i = 0; i < 16; i++) {
            int g = tid + i * 512;
            int node = g >> 6, j = g & 63;
            int ci = cd_s[node * 4 + (j >> 4)];
            sm[SM2_X + node * 100 + j] = w[ci * 16 + (j & 15)];
        }

        // ---- P2: PNA einsum (f32x2), 8 nodes per warp ----
        {
            int nw = warp * 8;
            const ull* W0 = (const ull*)(sm + SM2_WAGG + k * 3088) + d;
            const ulonglong2* T[8];
#pragma unroll
            for (int j = 0; j < 8; j++)
                T[j] = (const ulonglong2*)(sm + SM2_TMP + (nw + j) * 136 + k * 68);
            ull a0[8], a1[8], a2[8];
#pragma unroll
            for (int j = 0; j < 8; j++) { a0[j] = 0; a1[j] = 0; a2[j] = 0; }
#pragma unroll 2
            for (int f4 = 0; f4 < 16; f4++) {
                ull w00 = W0[(2 * f4) * 16],        w01 = W0[(2 * f4 + 1) * 16];
                ull w10 = W0[512 + (2 * f4) * 16],  w11 = W0[512 + (2 * f4 + 1) * 16];
                ull w20 = W0[1024 + (2 * f4) * 16], w21 = W0[1024 + (2 * f4 + 1) * 16];
#pragma unroll
                for (int j = 0; j < 8; j++) {
                    ulonglong2 v = T[j][f4];
                    fma2(a0[j], v.x, w00); fma2(a0[j], v.y, w01);
                    fma2(a1[j], v.x, w10); fma2(a1[j], v.y, w11);
                    fma2(a2[j], v.x, w20); fma2(a2[j], v.y, w21);
                }
            }
            float bg = sm[SM2_BAGG + lane];
#pragma unroll
            for (int j = 0; j < 8; j++) {
                int node = nw + j;
                sm[SM2_X + node * 100 + 64 + lane] =
                    bg + hsum2(a0[j]) + sm[SM2_AMP + node] * hsum2(a1[j])
                       + sm[SM2_ATT + node] * hsum2(a2[j]);
            }
        }
        __syncthreads();

        // ---- P4: h1 = relu(x @ W1 + b1), f32x2 ----
        float* h1_s = sm + SM2_TMP;
        {
            int nw = warp * 8;
            const ull* W1a = (const ull*)(sm + SM2_W1) + lane;
            const ulonglong2* X[8];
#pragma unroll
            for (int j = 0; j < 8; j++)
                X[j] = (const ulonglong2*)(sm + SM2_X + (nw + j) * 100);
            ull h0[8], h1r[8];
#pragma unroll
            for (int j = 0; j < 8; j++) { h0[j] = 0; h1r[j] = 0; }
#pragma unroll 2
            for (int f4 = 0; f4 < 24; f4++) {
                ull wa0 = W1a[(2 * f4) * 64],      wa1 = W1a[(2 * f4 + 1) * 64];
                ull wb0 = W1a[32 + (2 * f4) * 64], wb1 = W1a[32 + (2 * f4 + 1) * 64];
#pragma unroll
                for (int j = 0; j < 8; j++) {
                    ulonglong2 v = X[j][f4];
                    fma2(h0[j], v.x, wa0);  fma2(h0[j], v.y, wa1);
                    fma2(h1r[j], v.x, wb0); fma2(h1r[j], v.y, wb1);
                }
            }
            float b1a = sm[SM2_B1 + lane], b1b = sm[SM2_B1 + 32 + lane];
#pragma unroll
            for (int j = 0; j < 8; j++) {
                h1_s[(nw + j) * 68 + lane]      = fmaxf(hsum2(h0[j]) + b1a, 0.f);
                h1_s[(nw + j) * 68 + 32 + lane] = fmaxf(hsum2(h1r[j]) + b1b, 0.f);
            }
        }
        __syncwarp();

        // ---- P6: h2 = relu(h1 @ W2 + b2); deep partial = h2 * W3[lane] ----
        float gdeep[8];
        {
            int nw = warp * 8;
            const ull* W2p = (const ull*)(sm + SM2_W2) + lane;
            const ulonglong2* Hh[8];
#pragma unroll
            for (int j = 0; j < 8; j++)
                Hh[j] = (const ulonglong2*)(h1_s + (nw + j) * 68);
            ull a[8];
#pragma unroll
            for (int j = 0; j < 8; j++) a[j] = 0;
#pragma unroll 2
            for (int f4 = 0; f4 < 16; f4++) {
                ull wv0 = W2p[(2 * f4) * 32], wv1 = W2p[(2 * f4 + 1) * 32];
#pragma unroll
                for (int j = 0; j < 8; j++) {
                    ulonglong2 v = Hh[j][f4];
                    fma2(a[j], v.x, wv0); fma2(a[j], v.y, wv1);
                }
            }
            float b2v = sm[SM2_B2 + lane];
            float w3v = sm[SM2_W3 + lane];
#pragma unroll
            for (int j = 0; j < 8; j++)
                gdeep[j] = fmaxf(hsum2(a[j]) + b2v, 0.f) * w3v;
        }

        // ---- P7: lin + fm per node, reduce, output ----
        {
            float wl0 = sm[SM2_WLIN + lane], wl1 = sm[SM2_WLIN + 32 + lane], wl2 = sm[SM2_WLIN + 64 + lane];
            float bl = sm[SM2_MISC + 0] + sm[SM2_MISC + 1];
#pragma unroll
            for (int j = 0; j < 8; j++) {
                int node = warp * 8 + j;
                const float* xs = sm + SM2_X + node * 100;
                float e0 = xs[lane], e1 = xs[32 + lane], e2 = xs[64 + lane];
                float lin_p = e0 * wl0 + e1 * wl1 + e2 * wl2;
                float tsum = e0 + e1 + e2;
                float qsum = e0 * e0 + e1 * e1 + e2 * e2;
                float s = tsum + __shfl_xor_sync(0xffffffffu, tsum, 16);
                float qs = qsum + __shfl_xor_sync(0xffffffffu, qsum, 16);
                float r = lin_p + gdeep[j] + 0.25f * (s * s - qs);
#pragma unroll
                for (int o = 16; o; o >>= 1)
                    r += __shfl_xor_sync(0xffffffffu, r, o);
                int n = n0 + node;
                if (lane == 0 && n < Nd) {
                    float z = r + bl;
                    out[n] = 1.f / (1.f + expf(-z));
                    if (write_label) out[Nd + n] = (float)label[n];
                }
            }
        }
    }
}

// ---------------- launch ----------------------------------------------------
extern "C" void kernel_launch(void* const* d_in, const int* in_sizes, int n_in,
                              void* d_out, int out_size) {
    const int*   Cat_src = (const int*)  d_in[0];
    const int*   Cat_dst = (const int*)  d_in[1];
    const int*   src_ids = (const int*)  d_in[2];
    const int*   dst_ids = (const int*)  d_in[3];
    const int*   label   = (const int*)  d_in[4];
    const float* w       = (const float*)d_in[5];
    const float* W_agg   = (const float*)d_in[6];
    const float* b_agg   = (const float*)d_in[7];
    const float* w_lin   = (const float*)d_in[8];
    const float* b_lin   = (const float*)d_in[9];
    const float* W1      = (const float*)d_in[10];
    const float* b1      = (const float*)d_in[11];
    const float* W2      = (const float*)d_in[12];
    const float* b2      = (const float*)d_in[13];
    const float* W3      = (const float*)d_in[14];
    const float* b3      = (const float*)d_in[15];

    int Ns = in_sizes[0] / 4;
    int Nd = in_sizes[1] / 4;
    int E  = in_sizes[2];
    float* out = (float*)d_out;
    int write_label = (out_size >= 2 * Nd) ? 1 : 0;

    // 0: lookback reset + histogram + h_src
    k_pre<<<2048, 256>>>(Cat_src, dst_ids, w, E, Ns);
    // 1: fused CSR scan + fix (decoupled lookback)
    int nb = (Nd + 511) / 512;
    k_scan<<<nb, 512>>>(Nd, E);
    // 2: edge permutation (8 edges/thread)
    int e4 = (E + 3) / 4;
    k_scatter<<<(e4 + 511) / 512, 256>>>(src_ids, dst_ids, E);
    // 3: segment reduction (profiled slot)
    k_agg<<<(Nd + 15) / 16, 256>>>(Nd);
    // 4: einsum + DeepFM (f32x2, 128-node tiles)
    int ntiles = (Nd + 127) >> 7;
    size_t smem = SM2_TOTAL * sizeof(float);
    cudaFuncSetAttribute(k_mlp, cudaFuncAttributeMaxDynamicSharedMemorySize, (int)smem);
    k_mlp<<<ntiles, 512, smem>>>(Cat_dst, label, w,
                                 W_agg, b_agg, w_lin, b_lin,
                                 W1, b1, W2, b2, W3, b3,
                                 out, Nd, write_label);
}

// round 8
// speedup vs baseline: 1.9530x; 1.0932x over previous
#include <cuda_runtime.h>
#include <cuda_fp16.h>
#include <math.h>

typedef unsigned long long ull;

// ---------------- static scratch (no allocs) --------------------------------
#define NSMAX 1000000
#define NDMAX 100000
#define EMAX  3200000

__device__ int    g_deg[NDMAX];
__device__ int    g_rowptr[NDMAX + 1];
__device__ int    g_cursor[NDMAX];
__device__ int    g_look[1024];          // lookback state: bits28-29 state, low 28 value
__device__ int    g_perm[EMAX];
__device__ __half g_hsrc[NSMAX * 32];    // [Ns][d][mean,max] interleaved half2 pairs
__device__ float  g_tmp[NDMAX * 128];    // [Nd][k*64 + stat*16 + d]

#define LOG_AVG 3.4965075614664802f      // log(33.0)

// ---------------- f32x2 helpers ---------------------------------------------
__device__ __forceinline__ void fma2(ull& acc, ull a, ull b) {
    asm("fma.rn.f32x2 %0, %1, %2, %0;" : "+l"(acc) : "l"(a), "l"(b));
}
__device__ __forceinline__ float hsum2(ull v) {
    float lo, hi;
    asm("mov.b64 {%0,%1}, %2;" : "=f"(lo), "=f"(hi) : "l"(v));
    return lo + hi;
}

// ---------------- k_pre: reset lookback + histogram + h_src -----------------
__global__ __launch_bounds__(256) void k_pre(
    const int* __restrict__ Cat_src, const int* __restrict__ dst_ids,
    const float* __restrict__ w, int E, int Ns)
{
    int gtid = blockIdx.x * blockDim.x + threadIdx.x;
    int gstride = gridDim.x * blockDim.x;

    if (gtid < 1024) g_look[gtid] = 0;

    // histogram (int4 edge loads, streaming)
    int e4 = E >> 2;
    for (int i = gtid; i < e4; i += gstride) {
        int4 dd = __ldcs(&((const int4*)dst_ids)[i]);
        atomicAdd(&g_deg[dd.x], 1);
        atomicAdd(&g_deg[dd.y], 1);
        atomicAdd(&g_deg[dd.z], 1);
        atomicAdd(&g_deg[dd.w], 1);
    }
    if (gtid < (E & 3)) atomicAdd(&g_deg[dst_ids[e4 * 4 + gtid]], 1);

    // h_src: 4 nodes per warp-iteration (2 per half-warp), (mean,max) half2 layout
    int lane = threadIdx.x & 31;
    int half = lane >> 4;
    int j = lane & 15;
    __half2* H = (__half2*)g_hsrc;
    int gw = gtid >> 5;
    int wstride = gstride >> 5;
    int nquads = (Ns + 3) >> 2;
    for (int q = gw; q < nquads; q += wstride) {
        int nA = q * 4 + half;
        int nB = nA + 2;
        if (nA < Ns) {
            int4 cA = ((const int4*)Cat_src)[nA];
            int4 cB = (nB < Ns) ? ((const int4*)Cat_src)[nB] : cA;
            float a0 = w[cA.x * 16 + j], a1 = w[cA.y * 16 + j];
            float a2 = w[cA.z * 16 + j], a3 = w[cA.w * 16 + j];
            float b0 = w[cB.x * 16 + j], b1 = w[cB.y * 16 + j];
            float b2 = w[cB.z * 16 + j], b3 = w[cB.w * 16 + j];
            float meA = (a0 + a1 + a2 + a3) * 0.25f;
            float maA = fmaxf(fmaxf(a0, a1), fmaxf(a2, a3));
            float meB = (b0 + b1 + b2 + b3) * 0.25f;
            float maB = fmaxf(fmaxf(b0, b1), fmaxf(b2, b3));
            H[nA * 16 + j] = __floats2half2_rn(meA, maA);
            if (nB < Ns) H[nB * 16 + j] = __floats2half2_rn(meB, maB);
        }
    }
}

// ---------------- k_scan: fused scan + fix (decoupled lookback) -------------
__global__ __launch_bounds__(512) void k_scan(int nd, int E) {
    int b = blockIdx.x;
    int tid = threadIdx.x;
    int n = b * 512 + tid;
    int v = (n < nd) ? g_deg[n] : 0;
    int lane = tid & 31, wid = tid >> 5;

    int x = v;
#pragma unroll
    for (int o = 1; o < 32; o <<= 1) {
        int y = __shfl_up_sync(0xffffffffu, x, o);
        if (lane >= o) x += y;
    }
    __shared__ int ws[16];
    __shared__ int s_pre;
    if (lane == 31) ws[wid] = x;
    __syncthreads();
    if (wid == 0) {
        int s = (lane < 16) ? ws[lane] : 0;
#pragma unroll
        for (int o = 1; o < 16; o <<= 1) {
            int y = __shfl_up_sync(0xffffffffu, s, o);
            if (lane >= o) s += y;
        }
        if (lane < 16) ws[lane] = s;
    }
    __syncthreads();
    int off = wid ? ws[wid - 1] : 0;
    int incl = x + off;
    int total = ws[15];

    if (wid == 0) {
        if (b == 0) {
            if (lane == 0) {
                atomicExch(&g_look[0], (2 << 28) | total);
                s_pre = 0;
            }
        } else {
            if (lane == 0) atomicExch(&g_look[b], (1 << 28) | total);
            __syncwarp();
            int pre = 0;
            int idx = b - 1;
            while (true) {
                int i = idx - lane;
                int e;
                if (i >= 0) {
                    do { e = atomicAdd(&g_look[i], 0); } while ((e >> 28) == 0);
                } else {
                    e = (2 << 28);
                }
                unsigned pf = __ballot_sync(0xffffffffu, (e >> 28) == 2);
                int val = e & 0x0FFFFFFF;
                if (pf) {
                    int L = __ffs(pf) - 1;
                    int contrib = (lane <= L) ? val : 0;
#pragma unroll
                    for (int o = 16; o; o >>= 1) contrib += __shfl_xor_sync(0xffffffffu, contrib, o);
                    pre += contrib;
                    break;
                } else {
                    int contrib = val;
#pragma unroll
                    for (int o = 16; o; o >>= 1) contrib += __shfl_xor_sync(0xffffffffu, contrib, o);
                    pre += contrib;
                    idx -= 32;
                }
            }
            if (lane == 0) {
                atomicExch(&g_look[b], (2 << 28) | (pre + total));
                s_pre = pre;
            }
        }
    }
    __syncthreads();
    int pre = s_pre;

    if (n < nd) {
        int r = (incl - v) + pre;
        g_rowptr[n] = r;
        g_cursor[n] = r;
        g_deg[n] = 0;
        if (n == 0) g_rowptr[nd] = E;
    }
}

// ---------------- k_scatter: 8 edges per thread ------------------------------
__global__ __launch_bounds__(256) void k_scatter(
    const int* __restrict__ src, const int* __restrict__ dst, int E)
{
    int e4 = E >> 2;
#pragma unroll
    for (int u = 0; u < 2; u++) {
        int i = blockIdx.x * 512 + u * 256 + threadIdx.x;
        if (i < e4) {
            int4 s = __ldcs(&((const int4*)src)[i]);
            int4 d = __ldcs(&((const int4*)dst)[i]);
            g_perm[atomicAdd(&g_cursor[d.x], 1)] = s.x;
            g_perm[atomicAdd(&g_cursor[d.y], 1)] = s.y;
            g_perm[atomicAdd(&g_cursor[d.z], 1)] = s.z;
            g_perm[atomicAdd(&g_cursor[d.w], 1)] = s.w;
        }
    }
    int t = blockIdx.x * 512 + threadIdx.x;
    if (t < (E & 3)) {
        int e = e4 * 4 + t;
        g_perm[atomicAdd(&g_cursor[dst[e]], 1)] = src[e];
    }
}

// ---------------- k_agg: 2 dst-nodes per warp, half2 accumulate -------------
__global__ __launch_bounds__(256) void k_agg(int Nd)
{
    int lane = threadIdx.x & 31;
    int half = lane >> 4;
    int j = lane & 15;                   // d channel
    int n = (((blockIdx.x * 256 + threadIdx.x) >> 5) << 1) + half;
    if (n >= Nd) return;

    int base = g_rowptr[n], end = g_rowptr[n + 1];
    const __half2* H = (const __half2*)g_hsrc;

    __half2 s  = __floats2half2_rn(0.f, 0.f);
    __half2 q  = s;
    __half2 mn = __floats2half2_rn( 65504.f,  65504.f);
    __half2 mx = __floats2half2_rn(-65504.f, -65504.f);

    int i = base;
    // alignment prologue: advance until i is int4-aligned
    for (; i < end && (i & 3); i++) {
        __half2 a = H[g_perm[i] * 16 + j];
        s = __hadd2(s, a);
        q = __hfma2(a, a, q);
        mn = __hmin2(mn, a);
        mx = __hmax2(mx, a);
    }
    for (; i + 3 < end; i += 4) {
        int4 pp = *(const int4*)&g_perm[i];      // aligned (i%4==0)
        __half2 a = H[pp.x * 16 + j];
        __half2 b = H[pp.y * 16 + j];
        __half2 c = H[pp.z * 16 + j];
        __half2 e = H[pp.w * 16 + j];
        s = __hadd2(s, __hadd2(__hadd2(a, b), __hadd2(c, e)));
        q = __hfma2(a, a, q);
        q = __hfma2(b, b, q);
        q = __hfma2(c, c, q);
        q = __hfma2(e, e, q);
        mn = __hmin2(mn, __hmin2(__hmin2(a, b), __hmin2(c, e)));
        mx = __hmax2(mx, __hmax2(__hmax2(a, b), __hmax2(c, e)));
    }
    for (; i < end; i++) {
        __half2 a = H[g_perm[i] * 16 + j];
        s = __hadd2(s, a);
        q = __hfma2(a, a, q);
        mn = __hmin2(mn, a);
        mx = __hmax2(mx, a);
    }

    float2 sf = __half22float2(s);
    float2 qf = __half22float2(q);
    float2 mnf = __half22float2(mn);
    float2 mxf = __half22float2(mx);

    float deg = (float)(end - base);
    float inv = 1.f / fmaxf(deg, 1.f);
    bool has = deg > 0.f;
    float mean0 = sf.x * inv, mean1 = sf.y * inv;
    float sd0 = sqrtf(fmaxf(qf.x * inv - mean0 * mean0, 0.f) + 1e-5f);
    float sd1 = sqrtf(fmaxf(qf.y * inv - mean1 * mean1, 0.f) + 1e-5f);
    float mn0 = has ? mnf.x : 0.f, mn1 = has ? mnf.y : 0.f;
    float mx0 = has ? mxf.x : 0.f, mx1 = has ? mxf.y : 0.f;

    float* t = g_tmp + n * 128;
    t[j]       = mean0;  t[16 + j]  = mn0;  t[32 + j]  = mx0;  t[48 + j]  = sd0;
    t[64 + j]  = mean1;  t[80 + j]  = mn1;  t[96 + j]  = mx1;  t[112 + j] = sd1;
}

// ---------------- k_mlp: persistent, 128-node tiles, 8 nodes/warp, f32x2 ----
#define SM2_WAGG  0        // 6176
#define SM2_W1    6176     // 6144
#define SM2_W2    12320    // 2048
#define SM2_BAGG  14368    // 32
#define SM2_B1    14400    // 64
#define SM2_B2    14464    // 32
#define SM2_W3    14496    // 32
#define SM2_WLIN  14528    // 96
#define SM2_MISC  14624    // 2
#define SM2_AMP   14628    // 128
#define SM2_ATT   14756    // 128
#define SM2_CD    14884    // 512 ints
#define SM2_TMP   15396    // 128 nodes * 136 (k pitch 68); aliased by h1 (pitch 68)
#define SM2_X     32804    // 128 nodes * 100
#define SM2_TOTAL (32804 + 128 * 100)   // 45604 floats = 182416 B

__global__ __launch_bounds__(512, 1) void k_mlp(
    const int* __restrict__ Cat_dst, const int* __restrict__ label,
    const float* __restrict__ w,
    const float* __restrict__ W_agg, const float* __restrict__ b_agg,
    const float* __restrict__ w_lin, const float* __restrict__ b_lin,
    const float* __restrict__ W1, const float* __restrict__ b1,
    const float* __restrict__ W2, const float* __restrict__ b2,
    const float* __restrict__ W3, const float* __restrict__ b3,
    float* __restrict__ out, int Nd, int write_label)
{
    extern __shared__ float sm[];
    int tid = threadIdx.x;
    int lane = tid & 31, warp = tid >> 5;
    int k = lane >> 4, d = lane & 15;
    int* cd_s = (int*)(sm + SM2_CD);

    for (int i = tid; i < 6144; i += 512) {
        int kk = i / 3072;
        int r = i - kk * 3072;
        int sec = r >> 10;
        int rr = r & 1023;
        int ff = rr >> 4, dd = rr & 15;
        sm[SM2_WAGG + kk * 3088 + sec * 1024 + (ff >> 1) * 32 + dd * 2 + (ff & 1)] = W_agg[i];
        int f1 = i >> 6, o1 = i & 63;
        sm[SM2_W1 + (f1 >> 1) * 128 + o1 * 2 + (f1 & 1)] = W1[i];
    }
    for (int i = tid; i < 2048; i += 512) {
        int f2_ = i >> 5, o2 = i & 31;
        sm[SM2_W2 + (f2_ >> 1) * 64 + o2 * 2 + (f2_ & 1)] = W2[i];
    }
    if (tid < 32) { sm[SM2_BAGG + tid] = b_agg[tid]; sm[SM2_B2 + tid] = b2[tid]; sm[SM2_W3 + tid] = W3[tid]; }
    if (tid >= 32 && tid < 96) sm[SM2_B1 + tid - 32] = b1[tid - 32];
    if (tid >= 96 && tid < 192) sm[SM2_WLIN + tid - 96] = w_lin[tid - 96];
    if (tid == 192) { sm[SM2_MISC + 0] = b_lin[0]; sm[SM2_MISC + 1] = b3[0]; }
    __syncthreads();

    int ntiles = (Nd + 127) >> 7;
    for (int t = blockIdx.x; t < ntiles; t += gridDim.x) {
        int n0 = t << 7;
        __syncthreads();

        // ---- P1: stage tmp (128 nodes x 128), Cat_dst, amp/att ----
#pragma unroll
        for (int i = 0; i < 32; i++) {
            int g = tid + i * 512;
            int node = g >> 7, f = g & 127;
            int n = n0 + node; if (n >= Nd) n = Nd - 1;
            sm[SM2_TMP + node * 136 + (f >> 6) * 68 + (f & 63)] = __ldcs(&g_tmp[n * 128 + f]);
        }
        {
            int n = n0 + (tid >> 2); if (n >= Nd) n = Nd - 1;
            cd_s[tid] = Cat_dst[n * 4 + (tid & 3)];
        }
        if (tid < 128) {
            int n = n0 + tid; if (n >= Nd) n = Nd - 1;
            float deg = (float)(g_rowptr[n + 1] - g_rowptr[n]);
            float logd = logf(deg + 1.f);
            sm[SM2_AMP + tid] = logd * (1.f / LOG_AVG);
            sm[SM2_ATT + tid] = (logd > 0.f) ? (LOG_AVG / fmaxf(logd, 1e-5f)) : 0.f;
        }
        __syncthreads();

        // ---- P3: dst-embedding gathers into x[0..63] ----
#pragma unroll
        for (int i = 0; i < 16; i++) {
            int g = tid + i * 512;
            int node = g >> 6, j = g & 63;
            int ci = cd_s[node * 4 + (j >> 4)];
            sm[SM2_X + node * 100 + j] = w[ci * 16 + (j & 15)];
        }

        // ---- P2: PNA einsum (f32x2), 8 nodes per warp ----
        {
            int nw = warp * 8;
            const ull* W0 = (const ull*)(sm + SM2_WAGG + k * 3088) + d;
            const ulonglong2* T[8];
#pragma unroll
            for (int j = 0; j < 8; j++)
                T[j] = (const ulonglong2*)(sm + SM2_TMP + (nw + j) * 136 + k * 68);
            ull a0[8], a1[8], a2[8];
#pragma unroll
            for (int j = 0; j < 8; j++) { a0[j] = 0; a1[j] = 0; a2[j] = 0; }
#pragma unroll 2
            for (int f4 = 0; f4 < 16; f4++) {
                ull w00 = W0[(2 * f4) * 16],        w01 = W0[(2 * f4 + 1) * 16];
                ull w10 = W0[512 + (2 * f4) * 16],  w11 = W0[512 + (2 * f4 + 1) * 16];
                ull w20 = W0[1024 + (2 * f4) * 16], w21 = W0[1024 + (2 * f4 + 1) * 16];
#pragma unroll
                for (int j = 0; j < 8; j++) {
                    ulonglong2 v = T[j][f4];
                    fma2(a0[j], v.x, w00); fma2(a0[j], v.y, w01);
                    fma2(a1[j], v.x, w10); fma2(a1[j], v.y, w11);
                    fma2(a2[j], v.x, w20); fma2(a2[j], v.y, w21);
                }
            }
            float bg = sm[SM2_BAGG + lane];
#pragma unroll
            for (int j = 0; j < 8; j++) {
                int node = nw + j;
                sm[SM2_X + node * 100 + 64 + lane] =
                    bg + hsum2(a0[j]) + sm[SM2_AMP + node] * hsum2(a1[j])
                       + sm[SM2_ATT + node] * hsum2(a2[j]);
            }
        }
        __syncthreads();

        // ---- P4: h1 = relu(x @ W1 + b1), f32x2 ----
        float* h1_s = sm + SM2_TMP;
        {
            int nw = warp * 8;
            const ull* W1a = (const ull*)(sm + SM2_W1) + lane;
            const ulonglong2* X[8];
#pragma unroll
            for (int j = 0; j < 8; j++)
                X[j] = (const ulonglong2*)(sm + SM2_X + (nw + j) * 100);
            ull h0[8], h1r[8];
#pragma unroll
            for (int j = 0; j < 8; j++) { h0[j] = 0; h1r[j] = 0; }
#pragma unroll 2
            for (int f4 = 0; f4 < 24; f4++) {
                ull wa0 = W1a[(2 * f4) * 64],      wa1 = W1a[(2 * f4 + 1) * 64];
                ull wb0 = W1a[32 + (2 * f4) * 64], wb1 = W1a[32 + (2 * f4 + 1) * 64];
#pragma unroll
                for (int j = 0; j < 8; j++) {
                    ulonglong2 v = X[j][f4];
                    fma2(h0[j], v.x, wa0);  fma2(h0[j], v.y, wa1);
                    fma2(h1r[j], v.x, wb0); fma2(h1r[j], v.y, wb1);
                }
            }
            float b1a = sm[SM2_B1 + lane], b1b = sm[SM2_B1 + 32 + lane];
#pragma unroll
            for (int j = 0; j < 8; j++) {
                h1_s[(nw + j) * 68 + lane]      = fmaxf(hsum2(h0[j]) + b1a, 0.f);
                h1_s[(nw + j) * 68 + 32 + lane] = fmaxf(hsum2(h1r[j]) + b1b, 0.f);
            }
        }
        __syncwarp();

        // ---- P6: h2 = relu(h1 @ W2 + b2); deep partial = h2 * W3[lane] ----
        float gdeep[8];
        {
            int nw = warp * 8;
            const ull* W2p = (const ull*)(sm + SM2_W2) + lane;
            const ulonglong2* Hh[8];
#pragma unroll
            for (int j = 0; j < 8; j++)
                Hh[j] = (const ulonglong2*)(h1_s + (nw + j) * 68);
            ull a[8];
#pragma unroll
            for (int j = 0; j < 8; j++) a[j] = 0;
#pragma unroll 2
            for (int f4 = 0; f4 < 16; f4++) {
                ull wv0 = W2p[(2 * f4) * 32], wv1 = W2p[(2 * f4 + 1) * 32];
#pragma unroll
                for (int j = 0; j < 8; j++) {
                    ulonglong2 v = Hh[j][f4];
                    fma2(a[j], v.x, wv0); fma2(a[j], v.y, wv1);
                }
            }
            float b2v = sm[SM2_B2 + lane];
            float w3v = sm[SM2_W3 + lane];
#pragma unroll
            for (int j = 0; j < 8; j++)
                gdeep[j] = fmaxf(hsum2(a[j]) + b2v, 0.f) * w3v;
        }

        // ---- P7: lin + fm per node, reduce, output ----
        {
            float wl0 = sm[SM2_WLIN + lane], wl1 = sm[SM2_WLIN + 32 + lane], wl2 = sm[SM2_WLIN + 64 + lane];
            float bl = sm[SM2_MISC + 0] + sm[SM2_MISC + 1];
#pragma unroll
            for (int j = 0; j < 8; j++) {
                int node = warp * 8 + j;
                const float* xs = sm + SM2_X + node * 100;
                float e0 = xs[lane], e1 = xs[32 + lane], e2 = xs[64 + lane];
                float lin_p = e0 * wl0 + e1 * wl1 + e2 * wl2;
                float tsum = e0 + e1 + e2;
                float qsum = e0 * e0 + e1 * e1 + e2 * e2;
                float s = tsum + __shfl_xor_sync(0xffffffffu, tsum, 16);
                float qs = qsum + __shfl_xor_sync(0xffffffffu, qsum, 16);
                float r = lin_p + gdeep[j] + 0.25f * (s * s - qs);
#pragma unroll
                for (int o = 16; o; o >>= 1)
                    r += __shfl_xor_sync(0xffffffffu, r, o);
                int n = n0 + node;
                if (lane == 0 && n < Nd) {
                    float z = r + bl;
                    out[n] = 1.f / (1.f + expf(-z));
                    if (write_label) out[Nd + n] = (float)label[n];
                }
            }
        }
    }
}

// ---------------- launch ----------------------------------------------------
extern "C" void kernel_launch(void* const* d_in, const int* in_sizes, int n_in,
                              void* d_out, int out_size) {
    const int*   Cat_src = (const int*)  d_in[0];
    const int*   Cat_dst = (const int*)  d_in[1];
    const int*   src_ids = (const int*)  d_in[2];
    const int*   dst_ids = (const int*)  d_in[3];
    const int*   label   = (const int*)  d_in[4];
    const float* w       = (const float*)d_in[5];
    const float* W_agg   = (const float*)d_in[6];
    const float* b_agg   = (const float*)d_in[7];
    const float* w_lin   = (const float*)d_in[8];
    const float* b_lin   = (const float*)d_in[9];
    const float* W1      = (const float*)d_in[10];
    const float* b1      = (const float*)d_in[11];
    const float* W2      = (const float*)d_in[12];
    const float* b2      = (const float*)d_in[13];
    const float* W3      = (const float*)d_in[14];
    const float* b3      = (const float*)d_in[15];

    int Ns = in_sizes[0] / 4;
    int Nd = in_sizes[1] / 4;
    int E  = in_sizes[2];
    float* out = (float*)d_out;
    int write_label = (out_size >= 2 * Nd) ? 1 : 0;

    // 0: lookback reset + histogram + h_src
    k_pre<<<2048, 256>>>(Cat_src, dst_ids, w, E, Ns);
    // 1: fused CSR scan + fix (decoupled lookback)
    int nb = (Nd + 511) / 512;
    k_scan<<<nb, 512>>>(Nd, E);
    // 2: edge permutation (8 edges/thread)
    int e4 = (E + 3) / 4;
    k_scatter<<<(e4 + 511) / 512, 256>>>(src_ids, dst_ids, E);
    // 3: segment reduction (profiled slot)
    k_agg<<<(Nd + 15) / 16, 256>>>(Nd);
    // 4: einsum + DeepFM (f32x2, persistent grid)
    int ntiles = (Nd + 127) >> 7;
    int grid = ntiles < 148 ? ntiles : 148;
    size_t smem = SM2_TOTAL * sizeof(float);
    cudaFuncSetAttribute(k_mlp, cudaFuncAttributeMaxDynamicSharedMemorySize, (int)smem);
    k_mlp<<<grid, 512, smem>>>(Cat_dst, label, w,
                               W_agg, b_agg, w_lin, b_lin,
                               W1, b1, W2, b2, W3, b3,
                               out, Nd, write_label);
}

// round 9
// speedup vs baseline: 2.0006x; 1.0243x over previous
#include <cuda_runtime.h>
#include <cuda_fp16.h>
#include <math.h>

typedef unsigned long long ull;

// ---------------- static scratch (no allocs) --------------------------------
#define NSMAX 1000000
#define NDMAX 100000
#define EMAX  3200000

__device__ int    g_deg[NDMAX];
__device__ int    g_rowptr[NDMAX + 1];
__device__ int    g_cursor[NDMAX];
__device__ int    g_look[1024];          // lookback state: bits28-29 state, low 28 value
__device__ int    g_perm[EMAX];
__device__ __half g_hsrc[NSMAX * 32];    // [Ns][d][mean,max] interleaved half2 pairs
__device__ __half g_tmp[NDMAX * 128];    // [Nd][k*64 + stat*16 + d], fp16 (L2-resident)

#define LOG_AVG 3.4965075614664802f      // log(33.0)

// ---------------- f32x2 helpers ---------------------------------------------
__device__ __forceinline__ void fma2(ull& acc, ull a, ull b) {
    asm("fma.rn.f32x2 %0, %1, %2, %0;" : "+l"(acc) : "l"(a), "l"(b));
}
__device__ __forceinline__ float hsum2(ull v) {
    float lo, hi;
    asm("mov.b64 {%0,%1}, %2;" : "=f"(lo), "=f"(hi) : "l"(v));
    return lo + hi;
}

// ---------------- k_pre: reset lookback + histogram + h_src -----------------
__global__ __launch_bounds__(256) void k_pre(
    const int* __restrict__ Cat_src, const int* __restrict__ dst_ids,
    const float* __restrict__ w, int E, int Ns)
{
    int gtid = blockIdx.x * blockDim.x + threadIdx.x;
    int gstride = gridDim.x * blockDim.x;

    if (gtid < 1024) g_look[gtid] = 0;

    // histogram (int4 edge loads, streaming)
    int e4 = E >> 2;
    for (int i = gtid; i < e4; i += gstride) {
        int4 dd = __ldcs(&((const int4*)dst_ids)[i]);
        atomicAdd(&g_deg[dd.x], 1);
        atomicAdd(&g_deg[dd.y], 1);
        atomicAdd(&g_deg[dd.z], 1);
        atomicAdd(&g_deg[dd.w], 1);
    }
    if (gtid < (E & 3)) atomicAdd(&g_deg[dst_ids[e4 * 4 + gtid]], 1);

    // h_src: 4 nodes per warp-iteration (2 per half-warp), (mean,max) half2 layout
    int lane = threadIdx.x & 31;
    int half = lane >> 4;
    int j = lane & 15;
    __half2* H = (__half2*)g_hsrc;
    int gw = gtid >> 5;
    int wstride = gstride >> 5;
    int nquads = (Ns + 3) >> 2;
    for (int q = gw; q < nquads; q += wstride) {
        int nA = q * 4 + half;
        int nB = nA + 2;
        if (nA < Ns) {
            int4 cA = ((const int4*)Cat_src)[nA];
            int4 cB = (nB < Ns) ? ((const int4*)Cat_src)[nB] : cA;
            float a0 = w[cA.x * 16 + j], a1 = w[cA.y * 16 + j];
            float a2 = w[cA.z * 16 + j], a3 = w[cA.w * 16 + j];
            float b0 = w[cB.x * 16 + j], b1 = w[cB.y * 16 + j];
            float b2 = w[cB.z * 16 + j], b3 = w[cB.w * 16 + j];
            float meA = (a0 + a1 + a2 + a3) * 0.25f;
            float maA = fmaxf(fmaxf(a0, a1), fmaxf(a2, a3));
            float meB = (b0 + b1 + b2 + b3) * 0.25f;
            float maB = fmaxf(fmaxf(b0, b1), fmaxf(b2, b3));
            H[nA * 16 + j] = __floats2half2_rn(meA, maA);
            if (nB < Ns) H[nB * 16 + j] = __floats2half2_rn(meB, maB);
        }
    }
}

// ---------------- k_scan: fused scan + fix (decoupled lookback) -------------
__global__ __launch_bounds__(512) void k_scan(int nd, int E) {
    int b = blockIdx.x;
    int tid = threadIdx.x;
    int n = b * 512 + tid;
    int v = (n < nd) ? g_deg[n] : 0;
    int lane = tid & 31, wid = tid >> 5;

    int x = v;
#pragma unroll
    for (int o = 1; o < 32; o <<= 1) {
        int y = __shfl_up_sync(0xffffffffu, x, o);
        if (lane >= o) x += y;
    }
    __shared__ int ws[16];
    __shared__ int s_pre;
    if (lane == 31) ws[wid] = x;
    __syncthreads();
    if (wid == 0) {
        int s = (lane < 16) ? ws[lane] : 0;
#pragma unroll
        for (int o = 1; o < 16; o <<= 1) {
            int y = __shfl_up_sync(0xffffffffu, s, o);
            if (lane >= o) s += y;
        }
        if (lane < 16) ws[lane] = s;
    }
    __syncthreads();
    int off = wid ? ws[wid - 1] : 0;
    int incl = x + off;
    int total = ws[15];

    if (wid == 0) {
        if (b == 0) {
            if (lane == 0) {
                atomicExch(&g_look[0], (2 << 28) | total);
                s_pre = 0;
            }
        } else {
            if (lane == 0) atomicExch(&g_look[b], (1 << 28) | total);
            __syncwarp();
            int pre = 0;
            int idx = b - 1;
            while (true) {
                int i = idx - lane;
                int e;
                if (i >= 0) {
                    do { e = atomicAdd(&g_look[i], 0); } while ((e >> 28) == 0);
                } else {
                    e = (2 << 28);
                }
                unsigned pf = __ballot_sync(0xffffffffu, (e >> 28) == 2);
                int val = e & 0x0FFFFFFF;
                if (pf) {
                    int L = __ffs(pf) - 1;
                    int contrib = (lane <= L) ? val : 0;
#pragma unroll
                    for (int o = 16; o; o >>= 1) contrib += __shfl_xor_sync(0xffffffffu, contrib, o);
                    pre += contrib;
                    break;
                } else {
                    int contrib = val;
#pragma unroll
                    for (int o = 16; o; o >>= 1) contrib += __shfl_xor_sync(0xffffffffu, contrib, o);
                    pre += contrib;
                    idx -= 32;
                }
            }
            if (lane == 0) {
                atomicExch(&g_look[b], (2 << 28) | (pre + total));
                s_pre = pre;
            }
        }
    }
    __syncthreads();
    int pre = s_pre;

    if (n < nd) {
        int r = (incl - v) + pre;
        g_rowptr[n] = r;
        g_cursor[n] = r;
        g_deg[n] = 0;
        if (n == 0) g_rowptr[nd] = E;
    }
}

// ---------------- k_scatter: 8 edges per thread ------------------------------
__global__ __launch_bounds__(256) void k_scatter(
    const int* __restrict__ src, const int* __restrict__ dst, int E)
{
    int e4 = E >> 2;
#pragma unroll
    for (int u = 0; u < 2; u++) {
        int i = blockIdx.x * 512 + u * 256 + threadIdx.x;
        if (i < e4) {
            int4 s = __ldcs(&((const int4*)src)[i]);
            int4 d = __ldcs(&((const int4*)dst)[i]);
            g_perm[atomicAdd(&g_cursor[d.x], 1)] = s.x;
            g_perm[atomicAdd(&g_cursor[d.y], 1)] = s.y;
            g_perm[atomicAdd(&g_cursor[d.z], 1)] = s.z;
            g_perm[atomicAdd(&g_cursor[d.w], 1)] = s.w;
        }
    }
    int t = blockIdx.x * 512 + threadIdx.x;
    if (t < (E & 3)) {
        int e = e4 * 4 + t;
        g_perm[atomicAdd(&g_cursor[dst[e]], 1)] = src[e];
    }
}

// ---------------- k_agg: 2 dst-nodes per warp, half2 accumulate -------------
__global__ __launch_bounds__(256) void k_agg(int Nd)
{
    int lane = threadIdx.x & 31;
    int half = lane >> 4;
    int j = lane & 15;                   // d channel
    int n = (((blockIdx.x * 256 + threadIdx.x) >> 5) << 1) + half;
    if (n >= Nd) return;

    int base = g_rowptr[n], end = g_rowptr[n + 1];
    const __half2* H = (const __half2*)g_hsrc;

    __half2 s  = __floats2half2_rn(0.f, 0.f);
    __half2 q  = s;
    __half2 mn = __floats2half2_rn( 65504.f,  65504.f);
    __half2 mx = __floats2half2_rn(-65504.f, -65504.f);

    int i = base;
    for (; i < end && (i & 3); i++) {
        __half2 a = H[g_perm[i] * 16 + j];
        s = __hadd2(s, a);
        q = __hfma2(a, a, q);
        mn = __hmin2(mn, a);
        mx = __hmax2(mx, a);
    }
    for (; i + 3 < end; i += 4) {
        int4 pp = *(const int4*)&g_perm[i];      // aligned (i%4==0)
        __half2 a = H[pp.x * 16 + j];
        __half2 b = H[pp.y * 16 + j];
        __half2 c = H[pp.z * 16 + j];
        __half2 e = H[pp.w * 16 + j];
        s = __hadd2(s, __hadd2(__hadd2(a, b), __hadd2(c, e)));
        q = __hfma2(a, a, q);
        q = __hfma2(b, b, q);
        q = __hfma2(c, c, q);
        q = __hfma2(e, e, q);
        mn = __hmin2(mn, __hmin2(__hmin2(a, b), __hmin2(c, e)));
        mx = __hmax2(mx, __hmax2(__hmax2(a, b), __hmax2(c, e)));
    }
    for (; i < end; i++) {
        __half2 a = H[g_perm[i] * 16 + j];
        s = __hadd2(s, a);
        q = __hfma2(a, a, q);
        mn = __hmin2(mn, a);
        mx = __hmax2(mx, a);
    }

    float2 sf = __half22float2(s);
    float2 qf = __half22float2(q);
    float2 mnf = __half22float2(mn);
    float2 mxf = __half22float2(mx);

    float deg = (float)(end - base);
    float inv = 1.f / fmaxf(deg, 1.f);
    bool has = deg > 0.f;
    float mean0 = sf.x * inv, mean1 = sf.y * inv;
    float sd0 = sqrtf(fmaxf(qf.x * inv - mean0 * mean0, 0.f) + 1e-5f);
    float sd1 = sqrtf(fmaxf(qf.y * inv - mean1 * mean1, 0.f) + 1e-5f);
    float mn0 = has ? mnf.x : 0.f, mn1 = has ? mnf.y : 0.f;
    float mx0 = has ? mxf.x : 0.f, mx1 = has ? mxf.y : 0.f;

    __half* t = g_tmp + n * 128;
    t[j]       = __float2half_rn(mean0);
    t[16 + j]  = __float2half_rn(mn0);
    t[32 + j]  = __float2half_rn(mx0);
    t[48 + j]  = __float2half_rn(sd0);
    t[64 + j]  = __float2half_rn(mean1);
    t[80 + j]  = __float2half_rn(mn1);
    t[96 + j]  = __float2half_rn(mx1);
    t[112 + j] = __float2half_rn(sd1);
}

// ---------------- k_mlp: persistent, 128-node tiles, 8 nodes/warp, f32x2 ----
#define SM2_WAGG  0        // 6176
#define SM2_W1    6176     // 6144
#define SM2_W2    12320    // 2048
#define SM2_BAGG  14368    // 32
#define SM2_B1    14400    // 64
#define SM2_B2    14464    // 32
#define SM2_W3    14496    // 32
#define SM2_WLIN  14528    // 96
#define SM2_MISC  14624    // 2
#define SM2_AMP   14628    // 128
#define SM2_ATT   14756    // 128
#define SM2_CD    14884    // 512 ints
#define SM2_TMP   15396    // 128 nodes * 136 (k pitch 68); aliased by h1 (pitch 68)
#define SM2_X     32804    // 128 nodes * 100
#define SM2_TOTAL (32804 + 128 * 100)   // 45604 floats = 182416 B

__global__ __launch_bounds__(512, 1) void k_mlp(
    const int* __restrict__ Cat_dst, const int* __restrict__ label,
    const float* __restrict__ w,
    const float* __restrict__ W_agg, const float* __restrict__ b_agg,
    const float* __restrict__ w_lin, const float* __restrict__ b_lin,
    const float* __restrict__ W1, const float* __restrict__ b1,
    const float* __restrict__ W2, const float* __restrict__ b2,
    const float* __restrict__ W3, const float* __restrict__ b3,
    float* __restrict__ out, int Nd, int write_label)
{
    extern __shared__ float sm[];
    int tid = threadIdx.x;
    int lane = tid & 31, warp = tid >> 5;
    int k = lane >> 4, d = lane & 15;
    int* cd_s = (int*)(sm + SM2_CD);

    for (int i = tid; i < 6144; i += 512) {
        int kk = i / 3072;
        int r = i - kk * 3072;
        int sec = r >> 10;
        int rr = r & 1023;
        int ff = rr >> 4, dd = rr & 15;
        sm[SM2_WAGG + kk * 3088 + sec * 1024 + (ff >> 1) * 32 + dd * 2 + (ff & 1)] = W_agg[i];
        int f1 = i >> 6, o1 = i & 63;
        sm[SM2_W1 + (f1 >> 1) * 128 + o1 * 2 + (f1 & 1)] = W1[i];
    }
    for (int i = tid; i < 2048; i += 512) {
        int f2_ = i >> 5, o2 = i & 31;
        sm[SM2_W2 + (f2_ >> 1) * 64 + o2 * 2 + (f2_ & 1)] = W2[i];
    }
    if (tid < 32) { sm[SM2_BAGG + tid] = b_agg[tid]; sm[SM2_B2 + tid] = b2[tid]; sm[SM2_W3 + tid] = W3[tid]; }
    if (tid >= 32 && tid < 96) sm[SM2_B1 + tid - 32] = b1[tid - 32];
    if (tid >= 96 && tid < 192) sm[SM2_WLIN + tid - 96] = w_lin[tid - 96];
    if (tid == 192) { sm[SM2_MISC + 0] = b_lin[0]; sm[SM2_MISC + 1] = b3[0]; }
    __syncthreads();

    int ntiles = (Nd + 127) >> 7;
    for (int t = blockIdx.x; t < ntiles; t += gridDim.x) {
        int n0 = t << 7;
        __syncthreads();

        // ---- P1: stage tmp (128 nodes x 64 half2 pairs), Cat_dst, amp/att ----
#pragma unroll
        for (int i = 0; i < 16; i++) {
            int g = tid + i * 512;           // 8192 half2 pairs
            int node = g >> 6, f2p = g & 63;
            int n = n0 + node; if (n >= Nd) n = Nd - 1;
            float2 fv = __half22float2(__ldcs(&((const __half2*)(g_tmp + n * 128))[f2p]));
            int f = f2p * 2;                 // even; pair stays within one 64-block
            *(float2*)&sm[SM2_TMP + node * 136 + (f >> 6) * 68 + (f & 63)] = fv;
        }
        {
            int n = n0 + (tid >> 2); if (n >= Nd) n = Nd - 1;
            cd_s[tid] = Cat_dst[n * 4 + (tid & 3)];
        }
        if (tid < 128) {
            int n = n0 + tid; if (n >= Nd) n = Nd - 1;
            float deg = (float)(g_rowptr[n + 1] - g_rowptr[n]);
            float logd = logf(deg + 1.f);
            sm[SM2_AMP + tid] = logd * (1.f / LOG_AVG);
            sm[SM2_ATT + tid] = (logd > 0.f) ? (LOG_AVG / fmaxf(logd, 1e-5f)) : 0.f;
        }
        __syncthreads();

        // ---- P3: dst-embedding gathers into x[0..63] ----
#pragma unroll
        for (int i = 0; i < 16; i++) {
            int g = tid + i * 512;
            int node = g >> 6, j = g & 63;
            int ci = cd_s[node * 4 + (j >> 4)];
            sm[SM2_X + node * 100 + j] = w[ci * 16 + (j & 15)];
        }

        // ---- P2: PNA einsum (f32x2), 8 nodes per warp ----
        {
            int nw = warp * 8;
            const ull* W0 = (const ull*)(sm + SM2_WAGG + k * 3088) + d;
            const ulonglong2* T[8];
#pragma unroll
            for (int j = 0; j < 8; j++)
                T[j] = (const ulonglong2*)(sm + SM2_TMP + (nw + j) * 136 + k * 68);
            ull a0[8], a1[8], a2[8];
#pragma unroll
            for (int j = 0; j < 8; j++) { a0[j] = 0; a1[j] = 0; a2[j] = 0; }
#pragma unroll 2
            for (int f4 = 0; f4 < 16; f4++) {
                ull w00 = W0[(2 * f4) * 16],        w01 = W0[(2 * f4 + 1) * 16];
                ull w10 = W0[512 + (2 * f4) * 16],  w11 = W0[512 + (2 * f4 + 1) * 16];
                ull w20 = W0[1024 + (2 * f4) * 16], w21 = W0[1024 + (2 * f4 + 1) * 16];
#pragma unroll
                for (int j = 0; j < 8; j++) {
                    ulonglong2 v = T[j][f4];
                    fma2(a0[j], v.x, w00); fma2(a0[j], v.y, w01);
                    fma2(a1[j], v.x, w10); fma2(a1[j], v.y, w11);
                    fma2(a2[j], v.x, w20); fma2(a2[j], v.y, w21);
                }
            }
            float bg = sm[SM2_BAGG + lane];
#pragma unroll
            for (int j = 0; j < 8; j++) {
                int node = nw + j;
                sm[SM2_X + node * 100 + 64 + lane] =
                    bg + hsum2(a0[j]) + sm[SM2_AMP + node] * hsum2(a1[j])
                       + sm[SM2_ATT + node] * hsum2(a2[j]);
            }
        }
        __syncthreads();

        // ---- P4: h1 = relu(x @ W1 + b1), f32x2 ----
        float* h1_s = sm + SM2_TMP;
        {
            int nw = warp * 8;
            const ull* W1a = (const ull*)(sm + SM2_W1) + lane;
            const ulonglong2* X[8];
#pragma unroll
            for (int j = 0; j < 8; j++)
                X[j] = (const ulonglong2*)(sm + SM2_X + (nw + j) * 100);
            ull h0[8], h1r[8];
#pragma unroll
            for (int j = 0; j < 8; j++) { h0[j] = 0; h1r[j] = 0; }
#pragma unroll 2
            for (int f4 = 0; f4 < 24; f4++) {
                ull wa0 = W1a[(2 * f4) * 64],      wa1 = W1a[(2 * f4 + 1) * 64];
                ull wb0 = W1a[32 + (2 * f4) * 64], wb1 = W1a[32 + (2 * f4 + 1) * 64];
#pragma unroll
                for (int j = 0; j < 8; j++) {
                    ulonglong2 v = X[j][f4];
                    fma2(h0[j], v.x, wa0);  fma2(h0[j], v.y, wa1);
                    fma2(h1r[j], v.x, wb0); fma2(h1r[j], v.y, wb1);
                }
            }
            float b1a = sm[SM2_B1 + lane], b1b = sm[SM2_B1 + 32 + lane];
#pragma unroll
            for (int j = 0; j < 8; j++) {
                h1_s[(nw + j) * 68 + lane]      = fmaxf(hsum2(h0[j]) + b1a, 0.f);
                h1_s[(nw + j) * 68 + 32 + lane] = fmaxf(hsum2(h1r[j]) + b1b, 0.f);
            }
        }
        __syncwarp();

        // ---- P6: h2 = relu(h1 @ W2 + b2); deep partial = h2 * W3[lane] ----
        float gdeep[8];
        {
            int nw = warp * 8;
            const ull* W2p = (const ull*)(sm + SM2_W2) + lane;
            const ulonglong2* Hh[8];
#pragma unroll
            for (int j = 0; j < 8; j++)
                Hh[j] = (const ulonglong2*)(h1_s + (nw + j) * 68);
            ull a[8];
#pragma unroll
            for (int j = 0; j < 8; j++) a[j] = 0;
#pragma unroll 2
            for (int f4 = 0; f4 < 16; f4++) {
                ull wv0 = W2p[(2 * f4) * 32], wv1 = W2p[(2 * f4 + 1) * 32];
#pragma unroll
                for (int j = 0; j < 8; j++) {
                    ulonglong2 v = Hh[j][f4];
                    fma2(a[j], v.x, wv0); fma2(a[j], v.y, wv1);
                }
            }
            float b2v = sm[SM2_B2 + lane];
            float w3v = sm[SM2_W3 + lane];
#pragma unroll
            for (int j = 0; j < 8; j++)
                gdeep[j] = fmaxf(hsum2(a[j]) + b2v, 0.f) * w3v;
        }

        // ---- P7: lin + fm per node, reduce, output ----
        {
            float wl0 = sm[SM2_WLIN + lane], wl1 = sm[SM2_WLIN + 32 + lane], wl2 = sm[SM2_WLIN + 64 + lane];
            float bl = sm[SM2_MISC + 0] + sm[SM2_MISC + 1];
#pragma unroll
            for (int j = 0; j < 8; j++) {
                int node = warp * 8 + j;
                const float* xs = sm + SM2_X + node * 100;
                float e0 = xs[lane], e1 = xs[32 + lane], e2 = xs[64 + lane];
                float lin_p = e0 * wl0 + e1 * wl1 + e2 * wl2;
                float tsum = e0 + e1 + e2;
                float qsum = e0 * e0 + e1 * e1 + e2 * e2;
                float s = tsum + __shfl_xor_sync(0xffffffffu, tsum, 16);
                float qs = qsum + __shfl_xor_sync(0xffffffffu, qsum, 16);
                float r = lin_p + gdeep[j] + 0.25f * (s * s - qs);
#pragma unroll
                for (int o = 16; o; o >>= 1)
                    r += __shfl_xor_sync(0xffffffffu, r, o);
                int n = n0 + node;
                if (lane == 0 && n < Nd) {
                    float z = r + bl;
                    out[n] = 1.f / (1.f + expf(-z));
                    if (write_label) out[Nd + n] = (float)label[n];
                }
            }
        }
    }
}

// ---------------- launch ----------------------------------------------------
extern "C" void kernel_launch(void* const* d_in, const int* in_sizes, int n_in,
                              void* d_out, int out_size) {
    const int*   Cat_src = (const int*)  d_in[0];
    const int*   Cat_dst = (const int*)  d_in[1];
    const int*   src_ids = (const int*)  d_in[2];
    const int*   dst_ids = (const int*)  d_in[3];
    const int*   label   = (const int*)  d_in[4];
    const float* w       = (const float*)d_in[5];
    const float* W_agg   = (const float*)d_in[6];
    const float* b_agg   = (const float*)d_in[7];
    const float* w_lin   = (const float*)d_in[8];
    const float* b_lin   = (const float*)d_in[9];
    const float* W1      = (const float*)d_in[10];
    const float* b1      = (const float*)d_in[11];
    const float* W2      = (const float*)d_in[12];
    const float* b2      = (const float*)d_in[13];
    const float* W3      = (const float*)d_in[14];
    const float* b3      = (const float*)d_in[15];

    int Ns = in_sizes[0] / 4;
    int Nd = in_sizes[1] / 4;
    int E  = in_sizes[2];
    float* out = (float*)d_out;
    int write_label = (out_size >= 2 * Nd) ? 1 : 0;

    // 0: lookback reset + histogram + h_src
    k_pre<<<2048, 256>>>(Cat_src, dst_ids, w, E, Ns);
    // 1: fused CSR scan + fix (decoupled lookback)
    int nb = (Nd + 511) / 512;
    k_scan<<<nb, 512>>>(Nd, E);
    // 2: edge permutation (8 edges/thread)
    int e4 = (E + 3) / 4;
    k_scatter<<<(e4 + 511) / 512, 256>>>(src_ids, dst_ids, E);
    // 3: segment reduction (profiled slot)
    k_agg<<<(Nd + 15) / 16, 256>>>(Nd);
    // 4: einsum + DeepFM (f32x2, persistent grid)
    int ntiles = (Nd + 127) >> 7;
    int grid = ntiles < 148 ? ntiles : 148;
    size_t smem = SM2_TOTAL * sizeof(float);
    cudaFuncSetAttribute(k_mlp, cudaFuncAttributeMaxDynamicSharedMemorySize, (int)smem);
    k_mlp<<<grid, 512, smem>>>(Cat_dst, label, w,
                               W_agg, b_agg, w_lin, b_lin,
                               W1, b1, W2, b2, W3, b3,
                               out, Nd, write_label);
}